// round 1
// baseline (speedup 1.0000x reference)
#include <cuda_runtime.h>
#include <cuda_bf16.h>
#include <math.h>

#define B_   2
#define T_   2048
#define HID  2048
#define NH   16
#define NKV  4
#define HD   128

// Scratch (device globals — no allocation allowed)
__device__ float g_qo[(size_t)B_ * T_ * NH * HD];    // QKV-proj raw Q  [B*T, 2048]
__device__ float g_ko[(size_t)B_ * T_ * NKV * HD];   // raw K          [B*T, 512]
__device__ float g_vo[(size_t)B_ * T_ * NKV * HD];   // raw V          [B*T, 512]
__device__ float g_q [(size_t)B_ * NH  * T_ * HD];   // roped+scaled Q [B,16,T,128]
__device__ float g_k [(size_t)B_ * NKV * T_ * HD];   // roped K        [B,4,T,128]
__device__ float g_v [(size_t)B_ * NKV * T_ * HD];   // V              [B,4,T,128]
__device__ float g_attn[(size_t)B_ * T_ * NH * HD];  // attn out       [B*T, 2048]

// ---------------------------------------------------------------------------
// GEMM NT: C[M,N] = A[M,K] @ B[N,K]^T  (all row-major, M%128==0, N%128==0, K%16==0)
// 128x128 block tile, BK=16, 256 threads, 8x8 micro-tile per thread.
// Fragment split (tx*4 and 64+tx*4) keeps LDS.128 conflict-free.
// ---------------------------------------------------------------------------
__global__ __launch_bounds__(256) void gemm_nt(const float* __restrict__ A,
                                               const float* __restrict__ B,
                                               float* __restrict__ C,
                                               int M, int N, int K) {
    __shared__ float As[16][132];
    __shared__ float Bs[16][132];
    const int tid = threadIdx.x;
    const int tx = tid & 15, ty = tid >> 4;
    const int m0 = blockIdx.y * 128, n0 = blockIdx.x * 128;

    float acc[8][8];
#pragma unroll
    for (int i = 0; i < 8; ++i)
#pragma unroll
        for (int j = 0; j < 8; ++j) acc[i][j] = 0.f;

    const int nk = K >> 4;
    for (int kt = 0; kt < nk; ++kt) {
        const int k0 = kt << 4;
#pragma unroll
        for (int u = 0; u < 2; ++u) {
            int f   = tid * 2 + u;        // 0..511 float4 slots
            int row = f >> 2;             // 0..127
            int c4  = (f & 3) << 2;       // 0,4,8,12
            float4 av = *(const float4*)(A + (size_t)(m0 + row) * K + (k0 + c4));
            As[c4 + 0][row] = av.x; As[c4 + 1][row] = av.y;
            As[c4 + 2][row] = av.z; As[c4 + 3][row] = av.w;
            float4 bv = *(const float4*)(B + (size_t)(n0 + row) * K + (k0 + c4));
            Bs[c4 + 0][row] = bv.x; Bs[c4 + 1][row] = bv.y;
            Bs[c4 + 2][row] = bv.z; Bs[c4 + 3][row] = bv.w;
        }
        __syncthreads();
#pragma unroll
        for (int k = 0; k < 16; ++k) {
            float a[8], b[8];
            *(float4*)&a[0] = *(const float4*)&As[k][ty * 4];
            *(float4*)&a[4] = *(const float4*)&As[k][64 + ty * 4];
            *(float4*)&b[0] = *(const float4*)&Bs[k][tx * 4];
            *(float4*)&b[4] = *(const float4*)&Bs[k][64 + tx * 4];
#pragma unroll
            for (int i = 0; i < 8; ++i)
#pragma unroll
                for (int j = 0; j < 8; ++j) acc[i][j] += a[i] * b[j];
        }
        __syncthreads();
    }
#pragma unroll
    for (int i = 0; i < 8; ++i) {
        int row = m0 + ((i < 4) ? (ty * 4 + i) : (64 + ty * 4 + i - 4));
        float* Cr = C + (size_t)row * N + n0;
        *(float4*)(Cr + tx * 4)      = make_float4(acc[i][0], acc[i][1], acc[i][2], acc[i][3]);
        *(float4*)(Cr + 64 + tx * 4) = make_float4(acc[i][4], acc[i][5], acc[i][6], acc[i][7]);
    }
}

// ---------------------------------------------------------------------------
// RoPE + layout scatter. Accurate powf/sincosf keep angle error ~1e-4 rad.
// ---------------------------------------------------------------------------
__global__ void rope_q_kernel() {
    int idx = blockIdx.x * 256 + threadIdx.x;          // ((b*T+t)*16+h)*64+j
    int j = idx & 63;
    int h = (idx >> 6) & (NH - 1);
    int t = (idx >> 10) & (T_ - 1);
    int b = idx >> 21;
    float inv = powf(10000.0f, -(float)j / 64.0f);
    float s, c;
    sincosf((float)t * inv, &s, &c);
    const float scale = 0.08838834764831845f;          // 128^-0.5 folded into Q
    const float* src = g_qo + (size_t)(b * T_ + t) * (NH * HD) + h * HD;
    float x1 = src[j], x2 = src[j + 64];
    float* dst = g_q + ((size_t)(b * NH + h) * T_ + t) * HD;
    dst[j]      = (x1 * c - x2 * s) * scale;
    dst[j + 64] = (x2 * c + x1 * s) * scale;
}

__global__ void rope_k_kernel() {
    int idx = blockIdx.x * 256 + threadIdx.x;          // ((b*T+t)*4+kh)*64+j
    int j  = idx & 63;
    int kh = (idx >> 6) & (NKV - 1);
    int t  = (idx >> 8) & (T_ - 1);
    int b  = idx >> 19;
    float inv = powf(10000.0f, -(float)j / 64.0f);
    float s, c;
    sincosf((float)t * inv, &s, &c);
    const float* src = g_ko + (size_t)(b * T_ + t) * (NKV * HD) + kh * HD;
    float x1 = src[j], x2 = src[j + 64];
    float* dst = g_k + ((size_t)(b * NKV + kh) * T_ + t) * HD;
    dst[j]      = x1 * c - x2 * s;
    dst[j + 64] = x2 * c + x1 * s;
}

__global__ void copy_v_kernel() {
    int idx = blockIdx.x * 256 + threadIdx.x;          // ((b*T+t)*4+kh)*128+d
    int d  = idx & 127;
    int kh = (idx >> 7) & (NKV - 1);
    int t  = (idx >> 9) & (T_ - 1);
    int b  = idx >> 20;
    g_v[((size_t)(b * NKV + kh) * T_ + t) * HD + d] =
        g_vo[(size_t)(b * T_ + t) * (NKV * HD) + kh * HD + d];
}

// ---------------------------------------------------------------------------
// Flash attention (fp32, online softmax). BM=128 q-rows, BN=64 keys/iter.
// 256 threads; S micro-tile 8x4, O micro-tile 8x8. ~168 KB dynamic smem.
// ---------------------------------------------------------------------------
#define FBM 128
#define FBN 64

struct FlashSmem {
    float Qt[HD][FBM + 4];   // Q transposed [d][i]
    float Kt[HD][FBN + 4];   // K transposed [d][j]
    float Vs[FBN][HD + 4];   // V row-major  [j][d]
    float Ss[FBM][FBN + 4];  // scores / probabilities
    float row_m[FBM];
    float row_l[FBM];
    float row_a[FBM];
};

__global__ __launch_bounds__(256) void flash_kernel(const float* __restrict__ Q,
                                                    const float* __restrict__ K,
                                                    const float* __restrict__ V,
                                                    float* __restrict__ O) {
    extern __shared__ unsigned char smem_raw[];
    FlashSmem& sm = *reinterpret_cast<FlashSmem*>(smem_raw);
    const int tid = threadIdx.x;
    const int tx = tid & 15, ty = tid >> 4;
    const int b = blockIdx.z, h = blockIdx.y;
    const int q0 = blockIdx.x * FBM;
    const int kh = h >> 2;                                   // GQA group of 4

    const float* Qp = Q + ((size_t)(b * NH + h) * T_ + q0) * HD;
    const float* Kp = K + (size_t)(b * NKV + kh) * T_ * HD;
    const float* Vp = V + (size_t)(b * NKV + kh) * T_ * HD;

    // Load Q tile transposed
    for (int idx = tid; idx < FBM * HD / 4; idx += 256) {
        int i  = idx >> 5;
        int d4 = (idx & 31) << 2;
        float4 qv = *(const float4*)(Qp + (size_t)i * HD + d4);
        sm.Qt[d4 + 0][i] = qv.x; sm.Qt[d4 + 1][i] = qv.y;
        sm.Qt[d4 + 2][i] = qv.z; sm.Qt[d4 + 3][i] = qv.w;
    }
    if (tid < FBM) { sm.row_m[tid] = -1e30f; sm.row_l[tid] = 0.f; }

    int r_idx[8];
#pragma unroll
    for (int ri = 0; ri < 8; ++ri)
        r_idx[ri] = (ri < 4) ? (ty * 4 + ri) : (64 + ty * 4 + ri - 4);

    float oa[8][8];
#pragma unroll
    for (int i = 0; i < 8; ++i)
#pragma unroll
        for (int j = 0; j < 8; ++j) oa[i][j] = 0.f;

    const int ntiles = (q0 >> 6) + 2;                  // causal: only needed tiles
    for (int kt = 0; kt < ntiles; ++kt) {
        const int k0 = kt * FBN;
        __syncthreads();                               // prev-iter Ss/Vs/Kt done (also Qt ready)
        for (int idx = tid; idx < FBN * HD / 4; idx += 256) {
            int j  = idx >> 5;
            int d4 = (idx & 31) << 2;
            float4 kv = *(const float4*)(Kp + (size_t)(k0 + j) * HD + d4);
            sm.Kt[d4 + 0][j] = kv.x; sm.Kt[d4 + 1][j] = kv.y;
            sm.Kt[d4 + 2][j] = kv.z; sm.Kt[d4 + 3][j] = kv.w;
            *(float4*)&sm.Vs[j][d4] = *(const float4*)(Vp + (size_t)(k0 + j) * HD + d4);
        }
        __syncthreads();

        // S = Q K^T (Q already carries the 1/sqrt(D) scale)
        float sa[8][4];
#pragma unroll
        for (int i = 0; i < 8; ++i)
#pragma unroll
            for (int j = 0; j < 4; ++j) sa[i][j] = 0.f;
#pragma unroll 8
        for (int d = 0; d < HD; ++d) {
            float a[8], bb[4];
            *(float4*)&a[0]  = *(const float4*)&sm.Qt[d][ty * 4];
            *(float4*)&a[4]  = *(const float4*)&sm.Qt[d][64 + ty * 4];
            *(float4*)&bb[0] = *(const float4*)&sm.Kt[d][tx * 4];
#pragma unroll
            for (int i = 0; i < 8; ++i)
#pragma unroll
                for (int j = 0; j < 4; ++j) sa[i][j] += a[i] * bb[j];
        }
        // causal-masked store of S
#pragma unroll
        for (int ri = 0; ri < 8; ++ri) {
            int gi = q0 + r_idx[ri];
#pragma unroll
            for (int ci = 0; ci < 4; ++ci) {
                int gj = k0 + tx * 4 + ci;
                sm.Ss[r_idx[ri]][tx * 4 + ci] = (gj <= gi) ? sa[ri][ci] : -1e30f;
            }
        }
        __syncthreads();

        // Online softmax (one thread per row)
        if (tid < FBM) {
            const int r = tid;
            float mold = sm.row_m[r];
            float mx = mold;
#pragma unroll 8
            for (int j = 0; j < FBN; ++j) mx = fmaxf(mx, sm.Ss[r][j]);
            float alpha = __expf(mold - mx);
            float sum = 0.f;
#pragma unroll 8
            for (int j = 0; j < FBN; ++j) {
                float p = __expf(sm.Ss[r][j] - mx);
                sm.Ss[r][j] = p;
                sum += p;
            }
            sm.row_l[r] = sm.row_l[r] * alpha + sum;
            sm.row_m[r] = mx;
            sm.row_a[r] = alpha;
        }
        __syncthreads();

        // O = alpha*O + P V
        float al[8];
#pragma unroll
        for (int ri = 0; ri < 8; ++ri) al[ri] = sm.row_a[r_idx[ri]];
#pragma unroll
        for (int ri = 0; ri < 8; ++ri)
#pragma unroll
            for (int ci = 0; ci < 8; ++ci) oa[ri][ci] *= al[ri];
#pragma unroll 4
        for (int j = 0; j < FBN; ++j) {
            float4 v0 = *(const float4*)&sm.Vs[j][tx * 4];
            float4 v1 = *(const float4*)&sm.Vs[j][64 + tx * 4];
#pragma unroll
            for (int ri = 0; ri < 8; ++ri) {
                float p = sm.Ss[r_idx[ri]][j];
                oa[ri][0] += p * v0.x; oa[ri][1] += p * v0.y;
                oa[ri][2] += p * v0.z; oa[ri][3] += p * v0.w;
                oa[ri][4] += p * v1.x; oa[ri][5] += p * v1.y;
                oa[ri][6] += p * v1.z; oa[ri][7] += p * v1.w;
            }
        }
    }

    // Epilogue: normalize and store to [B*T, H*D] layout for the O-projection GEMM
#pragma unroll
    for (int ri = 0; ri < 8; ++ri) {
        int r = r_idx[ri];
        float invl = 1.0f / sm.row_l[r];
        float* op = O + (size_t)(b * T_ + q0 + r) * (NH * HD) + h * HD;
        *(float4*)(op + tx * 4) =
            make_float4(oa[ri][0] * invl, oa[ri][1] * invl, oa[ri][2] * invl, oa[ri][3] * invl);
        *(float4*)(op + 64 + tx * 4) =
            make_float4(oa[ri][4] * invl, oa[ri][5] * invl, oa[ri][6] * invl, oa[ri][7] * invl);
    }
}

// ---------------------------------------------------------------------------
// Launch: QKV GEMMs -> RoPE/scatter -> flash attention -> O projection
// ---------------------------------------------------------------------------
extern "C" void kernel_launch(void* const* d_in, const int* in_sizes, int n_in,
                              void* d_out, int out_size) {
    const float* x  = (const float*)d_in[0];
    // d_in[1] = mask: all-ones in the reference and unused by it — ignored.
    const float* Wq = (const float*)d_in[2];
    const float* Wk = (const float*)d_in[3];
    const float* Wv = (const float*)d_in[4];
    const float* Wo = (const float*)d_in[5];
    float* out = (float*)d_out;

    void *p_qo, *p_ko, *p_vo, *p_q, *p_k, *p_v, *p_attn;
    cudaGetSymbolAddress(&p_qo, g_qo);
    cudaGetSymbolAddress(&p_ko, g_ko);
    cudaGetSymbolAddress(&p_vo, g_vo);
    cudaGetSymbolAddress(&p_q,  g_q);
    cudaGetSymbolAddress(&p_k,  g_k);
    cudaGetSymbolAddress(&p_v,  g_v);
    cudaGetSymbolAddress(&p_attn, g_attn);

    cudaFuncSetAttribute(flash_kernel, cudaFuncAttributeMaxDynamicSharedMemorySize,
                         (int)sizeof(FlashSmem));

    // QKV projections: [4096,2048] @ W^T
    gemm_nt<<<dim3(16, 32), 256>>>(x, Wq, (float*)p_qo, B_ * T_, NH * HD, HID);
    gemm_nt<<<dim3(4, 32), 256>>>(x, Wk, (float*)p_ko, B_ * T_, NKV * HD, HID);
    gemm_nt<<<dim3(4, 32), 256>>>(x, Wv, (float*)p_vo, B_ * T_, NKV * HD, HID);

    rope_q_kernel<<<(B_ * T_ * NH * 64) / 256, 256>>>();
    rope_k_kernel<<<(B_ * T_ * NKV * 64) / 256, 256>>>();
    copy_v_kernel<<<(B_ * T_ * NKV * HD) / 256, 256>>>();

    flash_kernel<<<dim3(T_ / FBM, NH, B_), 256, sizeof(FlashSmem)>>>(
        (const float*)p_q, (const float*)p_k, (const float*)p_v, (float*)p_attn);

    // Output projection
    gemm_nt<<<dim3(16, 32), 256>>>((const float*)p_attn, Wo, out, B_ * T_, HID, HID);
}

// round 3
// speedup vs baseline: 1.3329x; 1.3329x over previous
#include <cuda_runtime.h>
#include <cuda_bf16.h>
#include <math.h>
#include <cstdint>

#define B_   2
#define T_   2048
#define HID  2048
#define NH   16
#define NKV  4
#define HD   128

// Scratch (device globals — no allocation allowed)
__device__ float g_qo[(size_t)B_ * T_ * NH * HD];    // QKV-proj raw Q  [B*T, 2048]
__device__ float g_ko[(size_t)B_ * T_ * NKV * HD];   // raw K          [B*T, 512]
__device__ float g_vo[(size_t)B_ * T_ * NKV * HD];   // raw V          [B*T, 512]
__device__ float g_q [(size_t)B_ * NH  * T_ * HD];   // roped+scaled Q [B,16,T,128]
__device__ float g_k [(size_t)B_ * NKV * T_ * HD];   // roped K        [B,4,T,128]
__device__ float g_v [(size_t)B_ * NKV * T_ * HD];   // V              [B,4,T,128]
__device__ float g_attn[(size_t)B_ * T_ * NH * HD];  // attn out       [B*T, 2048]

// ---------------------------------------------------------------------------
// bf16 split helpers: x ~= hi + lo, each bf16 (rn). Combined ~17 mantissa bits.
// ---------------------------------------------------------------------------
__device__ __forceinline__ void cvt_hilo(float4 v, uint2& hi, uint2& lo) {
    __nv_bfloat162 h0 = __floats2bfloat162_rn(v.x, v.y);
    __nv_bfloat162 h1 = __floats2bfloat162_rn(v.z, v.w);
    float rx = v.x - __bfloat162float(h0.x);
    float ry = v.y - __bfloat162float(h0.y);
    float rz = v.z - __bfloat162float(h1.x);
    float rw = v.w - __bfloat162float(h1.y);
    __nv_bfloat162 l0 = __floats2bfloat162_rn(rx, ry);
    __nv_bfloat162 l1 = __floats2bfloat162_rn(rz, rw);
    hi.x = *(uint32_t*)&h0; hi.y = *(uint32_t*)&h1;
    lo.x = *(uint32_t*)&l0; lo.y = *(uint32_t*)&l1;
}

// mma.sync m16n8k16 bf16 (f32 accum), D += A*B
__device__ __forceinline__ void mma_bf16(float* c, const uint32_t* a, const uint32_t* b) {
    asm volatile(
        "mma.sync.aligned.m16n8k16.row.col.f32.bf16.bf16.f32 "
        "{%0,%1,%2,%3}, {%4,%5,%6,%7}, {%8,%9}, {%0,%1,%2,%3};"
        : "+f"(c[0]), "+f"(c[1]), "+f"(c[2]), "+f"(c[3])
        : "r"(a[0]), "r"(a[1]), "r"(a[2]), "r"(a[3]), "r"(b[0]), "r"(b[1]));
}

// ---------------------------------------------------------------------------
// GEMM NT via mma.sync bf16x3: C[M,N] = A[M,K] @ B[N,K]^T (fp32 in/out)
// 128x128 CTA tile, BK=16, 8 warps (2m x 4n), warp tile 64x32.
// smem row = 16 data halves + 4 pad = 10 uint32 (40B) -> near-conflict-free LDS.
// Double-buffered. Planes: 0=A_hi 1=A_lo 2=B_hi 3=B_lo.
// ---------------------------------------------------------------------------
#define PLANE (128 * 10)

__global__ __launch_bounds__(256) void gemm_mma(const float* __restrict__ A,
                                                const float* __restrict__ Bm,
                                                float* __restrict__ C,
                                                int M, int N_, int K) {
    __shared__ __align__(16) uint32_t sm[2][4][PLANE];   // 40 KB
    const int tid = threadIdx.x;
    const int lane = tid & 31, wid = tid >> 5;
    const int g = lane >> 2, tg = lane & 3;
    const int m0 = blockIdx.y * 128, n0 = blockIdx.x * 128;
    const int mw = (wid >> 2) * 64, nw = (wid & 3) * 32;

    float acc[4][4][4];
#pragma unroll
    for (int mi = 0; mi < 4; ++mi)
#pragma unroll
        for (int nj = 0; nj < 4; ++nj)
#pragma unroll
            for (int r = 0; r < 4; ++r) acc[mi][nj][r] = 0.f;

    // global-load slots: s = tid*2+u; row=s>>2; kcol=(s&3)*4
    const int r_ld  = tid >> 1;               // row this thread loads (2 slots/row pair)
    float4 pa[2], pb[2];

    // prologue: load k-tile 0
#pragma unroll
    for (int u = 0; u < 2; ++u) {
        int s = tid * 2 + u;
        int rr = s >> 2, cc = (s & 3) << 2;
        pa[u] = *(const float4*)(A  + (size_t)(m0 + rr) * K + cc);
        pb[u] = *(const float4*)(Bm + (size_t)(n0 + rr) * K + cc);
    }
#pragma unroll
    for (int u = 0; u < 2; ++u) {
        int s = tid * 2 + u;
        int rr = s >> 2, cc = (s & 3) << 2;
        uint2 hi, lo;
        int w = rr * 10 + (cc >> 1);          // uint32 index in plane
        cvt_hilo(pa[u], hi, lo);
        *(uint2*)&sm[0][0][w] = hi;
        *(uint2*)&sm[0][1][w] = lo;
        cvt_hilo(pb[u], hi, lo);
        *(uint2*)&sm[0][2][w] = hi;
        *(uint2*)&sm[0][3][w] = lo;
    }
    __syncthreads();

    const int nkt = K >> 4;
    for (int kt = 0; kt < nkt; ++kt) {
        const int cur = kt & 1;
        // prefetch next k-tile into registers
        if (kt + 1 < nkt) {
            const int k0 = (kt + 1) << 4;
#pragma unroll
            for (int u = 0; u < 2; ++u) {
                int s = tid * 2 + u;
                int rr = s >> 2, cc = (s & 3) << 2;
                pa[u] = *(const float4*)(A  + (size_t)(m0 + rr) * K + (k0 + cc));
                pb[u] = *(const float4*)(Bm + (size_t)(n0 + rr) * K + (k0 + cc));
            }
        }

        // fragment loads
        uint32_t ah[4][4], al[4][4], bh[4][2], bl[4][2];
#pragma unroll
        for (int mi = 0; mi < 4; ++mi) {
            int base = (mw + mi * 16 + g) * 10 + tg;
            ah[mi][0] = sm[cur][0][base];
            ah[mi][1] = sm[cur][0][base + 80];
            ah[mi][2] = sm[cur][0][base + 4];
            ah[mi][3] = sm[cur][0][base + 84];
            al[mi][0] = sm[cur][1][base];
            al[mi][1] = sm[cur][1][base + 80];
            al[mi][2] = sm[cur][1][base + 4];
            al[mi][3] = sm[cur][1][base + 84];
        }
#pragma unroll
        for (int nj = 0; nj < 4; ++nj) {
            int base = (nw + nj * 8 + g) * 10 + tg;
            bh[nj][0] = sm[cur][2][base];
            bh[nj][1] = sm[cur][2][base + 4];
            bl[nj][0] = sm[cur][3][base];
            bl[nj][1] = sm[cur][3][base + 4];
        }

        // 3-pass bf16x3 MMA
#pragma unroll
        for (int mi = 0; mi < 4; ++mi)
#pragma unroll
            for (int nj = 0; nj < 4; ++nj) {
                mma_bf16(acc[mi][nj], ah[mi], bh[nj]);
                mma_bf16(acc[mi][nj], ah[mi], bl[nj]);
                mma_bf16(acc[mi][nj], al[mi], bh[nj]);
            }

        // store prefetched tile into other buffer
        if (kt + 1 < nkt) {
#pragma unroll
            for (int u = 0; u < 2; ++u) {
                int s = tid * 2 + u;
                int rr = s >> 2, cc = (s & 3) << 2;
                uint2 hi, lo;
                int w = rr * 10 + (cc >> 1);
                cvt_hilo(pa[u], hi, lo);
                *(uint2*)&sm[cur ^ 1][0][w] = hi;
                *(uint2*)&sm[cur ^ 1][1][w] = lo;
                cvt_hilo(pb[u], hi, lo);
                *(uint2*)&sm[cur ^ 1][2][w] = hi;
                *(uint2*)&sm[cur ^ 1][3][w] = lo;
            }
        }
        __syncthreads();
    }

    // epilogue: c0,c1 -> row g, cols tg*2,tg*2+1 ; c2,c3 -> row g+8
#pragma unroll
    for (int mi = 0; mi < 4; ++mi) {
#pragma unroll
        for (int nj = 0; nj < 4; ++nj) {
            int row = m0 + mw + mi * 16 + g;
            int col = n0 + nw + nj * 8 + tg * 2;
            *(float2*)(C + (size_t)row * N_ + col) =
                make_float2(acc[mi][nj][0], acc[mi][nj][1]);
            *(float2*)(C + (size_t)(row + 8) * N_ + col) =
                make_float2(acc[mi][nj][2], acc[mi][nj][3]);
        }
    }
    (void)r_ld;
}

// ---------------------------------------------------------------------------
// RoPE + layout scatter (unchanged)
// ---------------------------------------------------------------------------
__global__ void rope_q_kernel() {
    int idx = blockIdx.x * 256 + threadIdx.x;
    int j = idx & 63;
    int h = (idx >> 6) & (NH - 1);
    int t = (idx >> 10) & (T_ - 1);
    int b = idx >> 21;
    float inv = powf(10000.0f, -(float)j / 64.0f);
    float s, c;
    sincosf((float)t * inv, &s, &c);
    const float scale = 0.08838834764831845f;
    const float* src = g_qo + (size_t)(b * T_ + t) * (NH * HD) + h * HD;
    float x1 = src[j], x2 = src[j + 64];
    float* dst = g_q + ((size_t)(b * NH + h) * T_ + t) * HD;
    dst[j]      = (x1 * c - x2 * s) * scale;
    dst[j + 64] = (x2 * c + x1 * s) * scale;
}

__global__ void rope_k_kernel() {
    int idx = blockIdx.x * 256 + threadIdx.x;
    int j  = idx & 63;
    int kh = (idx >> 6) & (NKV - 1);
    int t  = (idx >> 8) & (T_ - 1);
    int b  = idx >> 19;
    float inv = powf(10000.0f, -(float)j / 64.0f);
    float s, c;
    sincosf((float)t * inv, &s, &c);
    const float* src = g_ko + (size_t)(b * T_ + t) * (NKV * HD) + kh * HD;
    float x1 = src[j], x2 = src[j + 64];
    float* dst = g_k + ((size_t)(b * NKV + kh) * T_ + t) * HD;
    dst[j]      = x1 * c - x2 * s;
    dst[j + 64] = x2 * c + x1 * s;
}

__global__ void copy_v_kernel() {
    int idx = blockIdx.x * 256 + threadIdx.x;
    int d  = idx & 127;
    int kh = (idx >> 7) & (NKV - 1);
    int t  = (idx >> 9) & (T_ - 1);
    int b  = idx >> 20;
    g_v[((size_t)(b * NKV + kh) * T_ + t) * HD + d] =
        g_vo[(size_t)(b * T_ + t) * (NKV * HD) + kh * HD + d];
}

// ---------------------------------------------------------------------------
// Flash attention (fp32, online softmax) — unchanged (known good)
// ---------------------------------------------------------------------------
#define FBM 128
#define FBN 64

struct FlashSmem {
    float Qt[HD][FBM + 4];
    float Kt[HD][FBN + 4];
    float Vs[FBN][HD + 4];
    float Ss[FBM][FBN + 4];
    float row_m[FBM];
    float row_l[FBM];
    float row_a[FBM];
};

__global__ __launch_bounds__(256) void flash_kernel(const float* __restrict__ Q,
                                                    const float* __restrict__ K,
                                                    const float* __restrict__ V,
                                                    float* __restrict__ O) {
    extern __shared__ unsigned char smem_raw[];
    FlashSmem& sm = *reinterpret_cast<FlashSmem*>(smem_raw);
    const int tid = threadIdx.x;
    const int tx = tid & 15, ty = tid >> 4;
    const int b = blockIdx.z, h = blockIdx.y;
    const int q0 = blockIdx.x * FBM;
    const int kh = h >> 2;

    const float* Qp = Q + ((size_t)(b * NH + h) * T_ + q0) * HD;
    const float* Kp = K + (size_t)(b * NKV + kh) * T_ * HD;
    const float* Vp = V + (size_t)(b * NKV + kh) * T_ * HD;

    for (int idx = tid; idx < FBM * HD / 4; idx += 256) {
        int i  = idx >> 5;
        int d4 = (idx & 31) << 2;
        float4 qv = *(const float4*)(Qp + (size_t)i * HD + d4);
        sm.Qt[d4 + 0][i] = qv.x; sm.Qt[d4 + 1][i] = qv.y;
        sm.Qt[d4 + 2][i] = qv.z; sm.Qt[d4 + 3][i] = qv.w;
    }
    if (tid < FBM) { sm.row_m[tid] = -1e30f; sm.row_l[tid] = 0.f; }

    int r_idx[8];
#pragma unroll
    for (int ri = 0; ri < 8; ++ri)
        r_idx[ri] = (ri < 4) ? (ty * 4 + ri) : (64 + ty * 4 + ri - 4);

    float oa[8][8];
#pragma unroll
    for (int i = 0; i < 8; ++i)
#pragma unroll
        for (int j = 0; j < 8; ++j) oa[i][j] = 0.f;

    const int ntiles = (q0 >> 6) + 2;
    for (int kt = 0; kt < ntiles; ++kt) {
        const int k0 = kt * FBN;
        __syncthreads();
        for (int idx = tid; idx < FBN * HD / 4; idx += 256) {
            int j  = idx >> 5;
            int d4 = (idx & 31) << 2;
            float4 kv = *(const float4*)(Kp + (size_t)(k0 + j) * HD + d4);
            sm.Kt[d4 + 0][j] = kv.x; sm.Kt[d4 + 1][j] = kv.y;
            sm.Kt[d4 + 2][j] = kv.z; sm.Kt[d4 + 3][j] = kv.w;
            *(float4*)&sm.Vs[j][d4] = *(const float4*)(Vp + (size_t)(k0 + j) * HD + d4);
        }
        __syncthreads();

        float sa[8][4];
#pragma unroll
        for (int i = 0; i < 8; ++i)
#pragma unroll
            for (int j = 0; j < 4; ++j) sa[i][j] = 0.f;
#pragma unroll 8
        for (int d = 0; d < HD; ++d) {
            float a[8], bb[4];
            *(float4*)&a[0]  = *(const float4*)&sm.Qt[d][ty * 4];
            *(float4*)&a[4]  = *(const float4*)&sm.Qt[d][64 + ty * 4];
            *(float4*)&bb[0] = *(const float4*)&sm.Kt[d][tx * 4];
#pragma unroll
            for (int i = 0; i < 8; ++i)
#pragma unroll
                for (int j = 0; j < 4; ++j) sa[i][j] += a[i] * bb[j];
        }
#pragma unroll
        for (int ri = 0; ri < 8; ++ri) {
            int gi = q0 + r_idx[ri];
#pragma unroll
            for (int ci = 0; ci < 4; ++ci) {
                int gj = k0 + tx * 4 + ci;
                sm.Ss[r_idx[ri]][tx * 4 + ci] = (gj <= gi) ? sa[ri][ci] : -1e30f;
            }
        }
        __syncthreads();

        if (tid < FBM) {
            const int r = tid;
            float mold = sm.row_m[r];
            float mx = mold;
#pragma unroll 8
            for (int j = 0; j < FBN; ++j) mx = fmaxf(mx, sm.Ss[r][j]);
            float alpha = __expf(mold - mx);
            float sum = 0.f;
#pragma unroll 8
            for (int j = 0; j < FBN; ++j) {
                float p = __expf(sm.Ss[r][j] - mx);
                sm.Ss[r][j] = p;
                sum += p;
            }
            sm.row_l[r] = sm.row_l[r] * alpha + sum;
            sm.row_m[r] = mx;
            sm.row_a[r] = alpha;
        }
        __syncthreads();

        float al[8];
#pragma unroll
        for (int ri = 0; ri < 8; ++ri) al[ri] = sm.row_a[r_idx[ri]];
#pragma unroll
        for (int ri = 0; ri < 8; ++ri)
#pragma unroll
            for (int ci = 0; ci < 8; ++ci) oa[ri][ci] *= al[ri];
#pragma unroll 4
        for (int j = 0; j < FBN; ++j) {
            float4 v0 = *(const float4*)&sm.Vs[j][tx * 4];
            float4 v1 = *(const float4*)&sm.Vs[j][64 + tx * 4];
#pragma unroll
            for (int ri = 0; ri < 8; ++ri) {
                float p = sm.Ss[r_idx[ri]][j];
                oa[ri][0] += p * v0.x; oa[ri][1] += p * v0.y;
                oa[ri][2] += p * v0.z; oa[ri][3] += p * v0.w;
                oa[ri][4] += p * v1.x; oa[ri][5] += p * v1.y;
                oa[ri][6] += p * v1.z; oa[ri][7] += p * v1.w;
            }
        }
    }

#pragma unroll
    for (int ri = 0; ri < 8; ++ri) {
        int r = r_idx[ri];
        float invl = 1.0f / sm.row_l[r];
        float* op = O + (size_t)(b * T_ + q0 + r) * (NH * HD) + h * HD;
        *(float4*)(op + tx * 4) =
            make_float4(oa[ri][0] * invl, oa[ri][1] * invl, oa[ri][2] * invl, oa[ri][3] * invl);
        *(float4*)(op + 64 + tx * 4) =
            make_float4(oa[ri][4] * invl, oa[ri][5] * invl, oa[ri][6] * invl, oa[ri][7] * invl);
    }
}

// ---------------------------------------------------------------------------
// Launch
// ---------------------------------------------------------------------------
extern "C" void kernel_launch(void* const* d_in, const int* in_sizes, int n_in,
                              void* d_out, int out_size) {
    const float* x  = (const float*)d_in[0];
    const float* Wq = (const float*)d_in[2];
    const float* Wk = (const float*)d_in[3];
    const float* Wv = (const float*)d_in[4];
    const float* Wo = (const float*)d_in[5];
    float* out = (float*)d_out;

    void *p_qo, *p_ko, *p_vo, *p_q, *p_k, *p_v, *p_attn;
    cudaGetSymbolAddress(&p_qo, g_qo);
    cudaGetSymbolAddress(&p_ko, g_ko);
    cudaGetSymbolAddress(&p_vo, g_vo);
    cudaGetSymbolAddress(&p_q,  g_q);
    cudaGetSymbolAddress(&p_k,  g_k);
    cudaGetSymbolAddress(&p_v,  g_v);
    cudaGetSymbolAddress(&p_attn, g_attn);

    cudaFuncSetAttribute(flash_kernel, cudaFuncAttributeMaxDynamicSharedMemorySize,
                         (int)sizeof(FlashSmem));

    // QKV projections on mma.sync bf16x3
    gemm_mma<<<dim3(16, 32), 256>>>(x, Wq, (float*)p_qo, B_ * T_, NH * HD, HID);
    gemm_mma<<<dim3(4, 32), 256>>>(x, Wk, (float*)p_ko, B_ * T_, NKV * HD, HID);
    gemm_mma<<<dim3(4, 32), 256>>>(x, Wv, (float*)p_vo, B_ * T_, NKV * HD, HID);

    rope_q_kernel<<<(B_ * T_ * NH * 64) / 256, 256>>>();
    rope_k_kernel<<<(B_ * T_ * NKV * 64) / 256, 256>>>();
    copy_v_kernel<<<(B_ * T_ * NKV * HD) / 256, 256>>>();

    flash_kernel<<<dim3(T_ / FBM, NH, B_), 256, sizeof(FlashSmem)>>>(
        (const float*)p_q, (const float*)p_k, (const float*)p_v, (float*)p_attn);

    // Output projection on mma.sync bf16x3
    gemm_mma<<<dim3(16, 32), 256>>>((const float*)p_attn, Wo, out, B_ * T_, HID, HID);
}

// round 8
// speedup vs baseline: 1.9306x; 1.4484x over previous
#include <cuda_runtime.h>
#include <cuda_bf16.h>
#include <math.h>
#include <cstdint>

#define B_   2
#define T_   2048
#define HID  2048
#define NH   16
#define NKV  4
#define HD   128

typedef __nv_bfloat16 bf16;
typedef __nv_bfloat162 bf162;

// ---------------------------------------------------------------------------
// Global scratch (device globals — no allocation allowed)
// ---------------------------------------------------------------------------
__device__ __align__(256) float g_qo[(size_t)B_ * T_ * NH * HD];
__device__ __align__(256) float g_ko[(size_t)B_ * T_ * NKV * HD];
__device__ __align__(256) float g_vo[(size_t)B_ * T_ * NKV * HD];

__device__ __align__(256) bf16 g_xh[(size_t)B_ * T_ * HID];
__device__ __align__(256) bf16 g_xl[(size_t)B_ * T_ * HID];
__device__ __align__(256) bf16 g_wqh[(size_t)HID * HID];
__device__ __align__(256) bf16 g_wql[(size_t)HID * HID];
__device__ __align__(256) bf16 g_wkh[(size_t)NKV * HD * HID];
__device__ __align__(256) bf16 g_wkl[(size_t)NKV * HD * HID];
__device__ __align__(256) bf16 g_wvh[(size_t)NKV * HD * HID];
__device__ __align__(256) bf16 g_wvl[(size_t)NKV * HD * HID];
__device__ __align__(256) bf16 g_woh[(size_t)HID * HID];
__device__ __align__(256) bf16 g_wol[(size_t)HID * HID];

__device__ __align__(256) bf16 g_qph[(size_t)B_ * NH * T_ * HD];
__device__ __align__(256) bf16 g_qpl[(size_t)B_ * NH * T_ * HD];
__device__ __align__(256) bf16 g_kph[(size_t)B_ * NKV * T_ * HD];
__device__ __align__(256) bf16 g_kpl[(size_t)B_ * NKV * T_ * HD];
__device__ __align__(256) bf16 g_vth[(size_t)B_ * NKV * HD * T_];
__device__ __align__(256) bf16 g_vtl[(size_t)B_ * NKV * HD * T_];
__device__ __align__(256) bf16 g_ah[(size_t)B_ * T_ * HID];
__device__ __align__(256) bf16 g_al[(size_t)B_ * T_ * HID];

// ---------------------------------------------------------------------------
// Helpers
// ---------------------------------------------------------------------------
__device__ __forceinline__ uint32_t smem_u32(const void* p) {
    uint32_t a;
    asm("{ .reg .u64 t; cvta.to.shared.u64 t, %1; cvt.u32.u64 %0, t; }"
        : "=r"(a) : "l"(p));
    return a;
}

#define CP_ASYNC16(dst, src) \
    asm volatile("cp.async.cg.shared.global [%0], [%1], 16;" :: "r"(dst), "l"(src))
#define CP_COMMIT() asm volatile("cp.async.commit_group;" ::: "memory")
#define CP_WAIT0()  asm volatile("cp.async.wait_group 0;" ::: "memory")

// mma.sync m16n8k16 bf16 (f32 accum), D += A*B
__device__ __forceinline__ void mma_bf16(float* c, const uint32_t* a, const uint32_t* b) {
    asm volatile(
        "mma.sync.aligned.m16n8k16.row.col.f32.bf16.bf16.f32 "
        "{%0,%1,%2,%3}, {%4,%5,%6,%7}, {%8,%9}, {%0,%1,%2,%3};"
        : "+f"(c[0]), "+f"(c[1]), "+f"(c[2]), "+f"(c[3])
        : "r"(a[0]), "r"(a[1]), "r"(a[2]), "r"(a[3]), "r"(b[0]), "r"(b[1]));
}

__device__ __forceinline__ void split1(float v, bf16& h, bf16& l) {
    h = __float2bfloat16(v);
    l = __float2bfloat16(v - __bfloat162float(h));
}

// ---------------------------------------------------------------------------
// Split pass: fp32 -> (hi, lo) bf16 planes
// ---------------------------------------------------------------------------
__global__ void split_kernel(const float* __restrict__ in, bf16* __restrict__ oh,
                             bf16* __restrict__ ol, int n4) {
    int i = blockIdx.x * 256 + threadIdx.x;
    if (i >= n4) return;
    float4 v = ((const float4*)in)[i];
    bf16 h0, l0, h1, l1, h2, l2, h3, l3;
    split1(v.x, h0, l0); split1(v.y, h1, l1);
    split1(v.z, h2, l2); split1(v.w, h3, l3);
    ((bf162*)oh)[2 * i]     = bf162(h0, h1);
    ((bf162*)oh)[2 * i + 1] = bf162(h2, h3);
    ((bf162*)ol)[2 * i]     = bf162(l0, l1);
    ((bf162*)ol)[2 * i + 1] = bf162(l2, l3);
}

// ---------------------------------------------------------------------------
// GEMM NT (pre-split planes): C[M,N] = A @ B^T, fp32 out.
// 128x128 tile, BK=16, 8 warps (2m x 4n), bf16x3, cp.async double-buffered.
// smem row stride = 12 u32 (48 B): 16B-aligned for cp.async AND conflict-free
// for fragment LDS ((12*r+tg) mod 32 tiles all banks).
// ---------------------------------------------------------------------------
#define GSTR 12
#define GPLANE (128 * GSTR)

__global__ __launch_bounds__(256) void gemm_bf(const bf16* __restrict__ Ah,
                                               const bf16* __restrict__ Al,
                                               const bf16* __restrict__ Bh,
                                               const bf16* __restrict__ Bl,
                                               float* __restrict__ C,
                                               int M, int N_, int K) {
    __shared__ __align__(16) uint32_t sm[2][4][GPLANE];   // 48 KB
    const int tid = threadIdx.x;
    const int lane = tid & 31, wid = tid >> 5;
    const int g = lane >> 2, tg = lane & 3;
    const int m0 = blockIdx.y * 128, n0 = blockIdx.x * 128;
    const int mw = (wid >> 2) * 64, nw = (wid & 3) * 32;

    float acc[4][4][4];
#pragma unroll
    for (int mi = 0; mi < 4; ++mi)
#pragma unroll
        for (int nj = 0; nj < 4; ++nj)
#pragma unroll
            for (int r = 0; r < 4; ++r) acc[mi][nj][r] = 0.f;

    const int rr = tid >> 1;            // row 0..127
    const int hc = (tid & 1) * 8;       // half-col 0 / 8
    const bf16* src[4] = {
        Ah + (size_t)(m0 + rr) * K + hc, Al + (size_t)(m0 + rr) * K + hc,
        Bh + (size_t)(n0 + rr) * K + hc, Bl + (size_t)(n0 + rr) * K + hc };
    uint32_t dst0[4];
#pragma unroll
    for (int p = 0; p < 4; ++p)
        dst0[p] = smem_u32(&sm[0][p][rr * GSTR + (tid & 1) * 4]);
    const uint32_t bufB = 4 * GPLANE * 4;

    // prologue: k-tile 0 -> buf0
#pragma unroll
    for (int p = 0; p < 4; ++p) CP_ASYNC16(dst0[p], src[p]);
    CP_COMMIT();

    const int nkt = K >> 4;
    for (int kt = 0; kt < nkt; ++kt) {
        CP_WAIT0();
        __syncthreads();
        if (kt + 1 < nkt) {
            const int k0 = (kt + 1) << 4;
            const uint32_t bo = ((kt + 1) & 1) * bufB;
#pragma unroll
            for (int p = 0; p < 4; ++p) CP_ASYNC16(dst0[p] + bo, src[p] + k0);
            CP_COMMIT();
        }
        const uint32_t (*cur)[GPLANE] = sm[kt & 1];

        uint32_t ah[4][4], al[4][4], bh[4][2], bl[4][2];
#pragma unroll
        for (int mi = 0; mi < 4; ++mi) {
            int base = (mw + mi * 16 + g) * GSTR + tg;
            ah[mi][0] = cur[0][base];      ah[mi][1] = cur[0][base + 8 * GSTR];
            ah[mi][2] = cur[0][base + 4];  ah[mi][3] = cur[0][base + 8 * GSTR + 4];
            al[mi][0] = cur[1][base];      al[mi][1] = cur[1][base + 8 * GSTR];
            al[mi][2] = cur[1][base + 4];  al[mi][3] = cur[1][base + 8 * GSTR + 4];
        }
#pragma unroll
        for (int nj = 0; nj < 4; ++nj) {
            int base = (nw + nj * 8 + g) * GSTR + tg;
            bh[nj][0] = cur[2][base]; bh[nj][1] = cur[2][base + 4];
            bl[nj][0] = cur[3][base]; bl[nj][1] = cur[3][base + 4];
        }
#pragma unroll
        for (int mi = 0; mi < 4; ++mi)
#pragma unroll
            for (int nj = 0; nj < 4; ++nj) {
                mma_bf16(acc[mi][nj], ah[mi], bh[nj]);
                mma_bf16(acc[mi][nj], ah[mi], bl[nj]);
                mma_bf16(acc[mi][nj], al[mi], bh[nj]);
            }
    }

#pragma unroll
    for (int mi = 0; mi < 4; ++mi) {
#pragma unroll
        for (int nj = 0; nj < 4; ++nj) {
            int row = m0 + mw + mi * 16 + g;
            int col = n0 + nw + nj * 8 + tg * 2;
            *(float2*)(C + (size_t)row * N_ + col) =
                make_float2(acc[mi][nj][0], acc[mi][nj][1]);
            *(float2*)(C + (size_t)(row + 8) * N_ + col) =
                make_float2(acc[mi][nj][2], acc[mi][nj][3]);
        }
    }
}

// ---------------------------------------------------------------------------
// RoPE -> bf16 hi/lo planes
// ---------------------------------------------------------------------------
__global__ void rope_q_kernel() {
    int idx = blockIdx.x * 256 + threadIdx.x;
    int j = idx & 63;
    int h = (idx >> 6) & (NH - 1);
    int t = (idx >> 10) & (T_ - 1);
    int b = idx >> 21;
    float inv = powf(10000.0f, -(float)j / 64.0f);
    float s, c;
    sincosf((float)t * inv, &s, &c);
    const float scale = 0.08838834764831845f;
    const float* src = g_qo + (size_t)(b * T_ + t) * (NH * HD) + h * HD;
    float x1 = src[j], x2 = src[j + 64];
    float y1 = (x1 * c - x2 * s) * scale;
    float y2 = (x2 * c + x1 * s) * scale;
    size_t o = ((size_t)(b * NH + h) * T_ + t) * HD;
    bf16 hh, ll;
    split1(y1, hh, ll); g_qph[o + j] = hh;      g_qpl[o + j] = ll;
    split1(y2, hh, ll); g_qph[o + j + 64] = hh; g_qpl[o + j + 64] = ll;
}

__global__ void rope_k_kernel() {
    int idx = blockIdx.x * 256 + threadIdx.x;
    int j  = idx & 63;
    int kh = (idx >> 6) & (NKV - 1);
    int t  = (idx >> 8) & (T_ - 1);
    int b  = idx >> 19;
    float inv = powf(10000.0f, -(float)j / 64.0f);
    float s, c;
    sincosf((float)t * inv, &s, &c);
    const float* src = g_ko + (size_t)(b * T_ + t) * (NKV * HD) + kh * HD;
    float x1 = src[j], x2 = src[j + 64];
    float y1 = x1 * c - x2 * s;
    float y2 = x2 * c + x1 * s;
    size_t o = ((size_t)(b * NKV + kh) * T_ + t) * HD;
    bf16 hh, ll;
    split1(y1, hh, ll); g_kph[o + j] = hh;      g_kpl[o + j] = ll;
    split1(y2, hh, ll); g_kph[o + j + 64] = hh; g_kpl[o + j + 64] = ll;
}

// ---------------------------------------------------------------------------
// V transpose: g_vo [b*T+t][kh*128+d] fp32 -> Vt planes [(b,kh)*128+d][T] bf16
// ---------------------------------------------------------------------------
__global__ void vt_kernel() {
    __shared__ float tl[32][33];
    int tx = threadIdx.x, ty = threadIdx.y;
    int t0 = blockIdx.x * 32, d0 = blockIdx.y * 32, bk = blockIdx.z;
    int b = bk >> 2, kh = bk & 3;
#pragma unroll
    for (int i = 0; i < 4; ++i)
        tl[ty + 8 * i][tx] =
            g_vo[(size_t)(b * T_ + t0 + ty + 8 * i) * (NKV * HD) + kh * HD + d0 + tx];
    __syncthreads();
#pragma unroll
    for (int i = 0; i < 4; ++i) {
        int dd = ty + 8 * i;
        float v = tl[tx][dd];
        bf16 hh, ll;
        split1(v, hh, ll);
        size_t o = ((size_t)bk * HD + d0 + dd) * T_ + t0 + tx;
        g_vth[o] = hh;
        g_vtl[o] = ll;
    }
}

// ---------------------------------------------------------------------------
// Flash attention on mma.sync bf16x3. BM=128, BN=64, HD=128, 256 threads.
// ---------------------------------------------------------------------------
#define QSTR 68   // u32 per Q/K smem row (272 B, 16-multiple)
#define PSTR 36   // u32 per P/Vt smem row (144 B, 16-multiple)
#define SSTR 68   // floats per S row

struct FlashSmem2 {
    uint32_t Qh[128 * QSTR], Ql[128 * QSTR];
    uint32_t Kh[64 * QSTR],  Kl[64 * QSTR];
    uint32_t Vh[128 * PSTR], Vl[128 * PSTR];
    float    Ss[128 * SSTR];
    uint32_t Ph[128 * PSTR], Pl[128 * PSTR];
    float row_m[128], row_l[128], row_a[128];
};
static_assert(sizeof(FlashSmem2) <= 227 * 1024, "smem too big");

__global__ __launch_bounds__(256, 1) void flash_mma(float* dummy) {
    extern __shared__ unsigned char smraw[];
    FlashSmem2& sm = *reinterpret_cast<FlashSmem2*>(smraw);
    const int tid = threadIdx.x;
    const int lane = tid & 31, wid = tid >> 5;
    const int g = lane >> 2, tg = lane & 3;
    const int b = blockIdx.z, h = blockIdx.y;
    const int q0 = blockIdx.x * 128;
    const int kh = h >> 2;
    const int wm = wid >> 1, wn = wid & 1;    // S: 4x2 warp grid (32x32 tiles)
    const int wn2 = wid & 1;                  // O: 4x2 warp grid (32x64 tiles)

    const bf16* Qhg = g_qph + ((size_t)(b * NH + h) * T_ + q0) * HD;
    const bf16* Qlg = g_qpl + ((size_t)(b * NH + h) * T_ + q0) * HD;
    const bf16* Khg = g_kph + (size_t)(b * NKV + kh) * T_ * HD;
    const bf16* Klg = g_kpl + (size_t)(b * NKV + kh) * T_ * HD;
    const bf16* Vhg = g_vth + (size_t)(b * NKV + kh) * HD * T_;
    const bf16* Vlg = g_vtl + (size_t)(b * NKV + kh) * HD * T_;

    // Load Q tile (128 x 128 halves per plane)
    for (int s = tid; s < 128 * 16; s += 256) {
        int row = s >> 4, c16 = s & 15;
        *(uint4*)&sm.Qh[row * QSTR + c16 * 4] = *(const uint4*)(Qhg + (size_t)row * HD + c16 * 8);
        *(uint4*)&sm.Ql[row * QSTR + c16 * 4] = *(const uint4*)(Qlg + (size_t)row * HD + c16 * 8);
    }
    if (tid < 128) { sm.row_m[tid] = -1e30f; sm.row_l[tid] = 0.f; }

    float co[2][8][4];
#pragma unroll
    for (int mi = 0; mi < 2; ++mi)
#pragma unroll
        for (int nj = 0; nj < 8; ++nj)
#pragma unroll
            for (int r = 0; r < 4; ++r) co[mi][nj][r] = 0.f;

    const uint32_t khb = smem_u32(sm.Kh), klb = smem_u32(sm.Kl);
    const uint32_t vhb = smem_u32(sm.Vh), vlb = smem_u32(sm.Vl);

    const int ntiles = (q0 >> 6) + 2;
    for (int kt = 0; kt < ntiles; ++kt) {
        const int k0 = kt * 64;
        __syncthreads();   // prev O-phase done with Vh/Vl; Q ready on iter 0

        for (int s = tid; s < 64 * 16; s += 256) {
            int row = s >> 4, c16 = s & 15;
            const bf16* gk = Khg + (size_t)(k0 + row) * HD + c16 * 8;
            CP_ASYNC16(khb + (row * QSTR + c16 * 4) * 4, gk);
            const bf16* gl = Klg + (size_t)(k0 + row) * HD + c16 * 8;
            CP_ASYNC16(klb + (row * QSTR + c16 * 4) * 4, gl);
        }
        for (int s = tid; s < 128 * 8; s += 256) {
            int d = s >> 3, c8 = s & 7;
            const bf16* gv = Vhg + (size_t)d * T_ + k0 + c8 * 8;
            CP_ASYNC16(vhb + (d * PSTR + c8 * 4) * 4, gv);
            const bf16* gl = Vlg + (size_t)d * T_ + k0 + c8 * 8;
            CP_ASYNC16(vlb + (d * PSTR + c8 * 4) * 4, gl);
        }
        CP_COMMIT();
        CP_WAIT0();
        __syncthreads();

        // ---- S = Q K^T (bf16x3), warp tile 32x32 ----
        float cs[2][4][4];
#pragma unroll
        for (int mi = 0; mi < 2; ++mi)
#pragma unroll
            for (int nj = 0; nj < 4; ++nj)
#pragma unroll
                for (int r = 0; r < 4; ++r) cs[mi][nj][r] = 0.f;

#pragma unroll
        for (int kf = 0; kf < 8; ++kf) {
            uint32_t qh[2][4], ql[2][4];
#pragma unroll
            for (int mi = 0; mi < 2; ++mi) {
                int ab = (wm * 32 + mi * 16 + g) * QSTR + kf * 8 + tg;
                qh[mi][0] = sm.Qh[ab];       qh[mi][1] = sm.Qh[ab + 8 * QSTR];
                qh[mi][2] = sm.Qh[ab + 4];   qh[mi][3] = sm.Qh[ab + 8 * QSTR + 4];
                ql[mi][0] = sm.Ql[ab];       ql[mi][1] = sm.Ql[ab + 8 * QSTR];
                ql[mi][2] = sm.Ql[ab + 4];   ql[mi][3] = sm.Ql[ab + 8 * QSTR + 4];
            }
#pragma unroll
            for (int nj = 0; nj < 4; ++nj) {
                int bb = (wn * 32 + nj * 8 + g) * QSTR + kf * 8 + tg;
                uint32_t kh2[2] = { sm.Kh[bb], sm.Kh[bb + 4] };
                uint32_t kl2[2] = { sm.Kl[bb], sm.Kl[bb + 4] };
#pragma unroll
                for (int mi = 0; mi < 2; ++mi) {
                    mma_bf16(cs[mi][nj], qh[mi], kh2);
                    mma_bf16(cs[mi][nj], qh[mi], kl2);
                    mma_bf16(cs[mi][nj], ql[mi], kh2);
                }
            }
        }
        // masked write of S
#pragma unroll
        for (int mi = 0; mi < 2; ++mi) {
#pragma unroll
            for (int nj = 0; nj < 4; ++nj) {
                int row = wm * 32 + mi * 16 + g;
                int col = wn * 32 + nj * 8 + tg * 2;
                int gi0 = q0 + row, gi1 = gi0 + 8;
                int gj0 = k0 + col, gj1 = gj0 + 1;
                sm.Ss[row * SSTR + col]     = (gj0 <= gi0) ? cs[mi][nj][0] : -1e30f;
                sm.Ss[row * SSTR + col + 1] = (gj1 <= gi0) ? cs[mi][nj][1] : -1e30f;
                sm.Ss[(row + 8) * SSTR + col]     = (gj0 <= gi1) ? cs[mi][nj][2] : -1e30f;
                sm.Ss[(row + 8) * SSTR + col + 1] = (gj1 <= gi1) ? cs[mi][nj][3] : -1e30f;
            }
        }
        __syncthreads();

        // ---- online softmax, P -> bf16 hi/lo ----
        if (tid < 128) {
            const int r = tid;
            float mold = sm.row_m[r];
            float mx = mold;
#pragma unroll 8
            for (int j = 0; j < 64; ++j) mx = fmaxf(mx, sm.Ss[r * SSTR + j]);
            float alpha = __expf(mold - mx);
            float sum = 0.f;
            bf16* phr = (bf16*)sm.Ph + r * (2 * PSTR);
            bf16* plr = (bf16*)sm.Pl + r * (2 * PSTR);
#pragma unroll 8
            for (int j = 0; j < 64; ++j) {
                float p = __expf(sm.Ss[r * SSTR + j] - mx);
                bf16 hh, ll;
                split1(p, hh, ll);
                phr[j] = hh;
                plr[j] = ll;
                sum += p;
            }
            sm.row_l[r] = sm.row_l[r] * alpha + sum;
            sm.row_m[r] = mx;
            sm.row_a[r] = alpha;
        }
        __syncthreads();

        // ---- O = alpha*O + P V (bf16x3), warp tile 32x64 ----
        float a0[2], a1[2];
#pragma unroll
        for (int mi = 0; mi < 2; ++mi) {
            a0[mi] = sm.row_a[wm * 32 + mi * 16 + g];
            a1[mi] = sm.row_a[wm * 32 + mi * 16 + g + 8];
        }
#pragma unroll
        for (int mi = 0; mi < 2; ++mi)
#pragma unroll
            for (int nj = 0; nj < 8; ++nj) {
                co[mi][nj][0] *= a0[mi]; co[mi][nj][1] *= a0[mi];
                co[mi][nj][2] *= a1[mi]; co[mi][nj][3] *= a1[mi];
            }
#pragma unroll
        for (int kf = 0; kf < 4; ++kf) {
            uint32_t ph[2][4], pl[2][4];
#pragma unroll
            for (int mi = 0; mi < 2; ++mi) {
                int ab = (wm * 32 + mi * 16 + g) * PSTR + kf * 8 + tg;
                ph[mi][0] = sm.Ph[ab];     ph[mi][1] = sm.Ph[ab + 8 * PSTR];
                ph[mi][2] = sm.Ph[ab + 4]; ph[mi][3] = sm.Ph[ab + 8 * PSTR + 4];
                pl[mi][0] = sm.Pl[ab];     pl[mi][1] = sm.Pl[ab + 8 * PSTR];
                pl[mi][2] = sm.Pl[ab + 4]; pl[mi][3] = sm.Pl[ab + 8 * PSTR + 4];
            }
#pragma unroll
            for (int nj = 0; nj < 8; ++nj) {
                int bb = (wn2 * 64 + nj * 8 + g) * PSTR + kf * 8 + tg;
                uint32_t vh2[2] = { sm.Vh[bb], sm.Vh[bb + 4] };
                uint32_t vl2[2] = { sm.Vl[bb], sm.Vl[bb + 4] };
#pragma unroll
                for (int mi = 0; mi < 2; ++mi) {
                    mma_bf16(co[mi][nj], ph[mi], vh2);
                    mma_bf16(co[mi][nj], ph[mi], vl2);
                    mma_bf16(co[mi][nj], pl[mi], vh2);
                }
            }
        }
    }

    // ---- epilogue: normalize, split to attn hi/lo planes ----
#pragma unroll
    for (int mi = 0; mi < 2; ++mi) {
        int r0 = wm * 32 + mi * 16 + g;
        int r1 = r0 + 8;
        float i0 = 1.0f / sm.row_l[r0];
        float i1 = 1.0f / sm.row_l[r1];
#pragma unroll
        for (int nj = 0; nj < 8; ++nj) {
            int col = wn2 * 64 + nj * 8 + tg * 2;
            size_t o0 = (size_t)(b * T_ + q0 + r0) * HID + h * HD + col;
            size_t o1 = (size_t)(b * T_ + q0 + r1) * HID + h * HD + col;
            bf16 h0, l0, h1, l1;
            split1(co[mi][nj][0] * i0, h0, l0);
            split1(co[mi][nj][1] * i0, h1, l1);
            *(bf162*)&g_ah[o0] = bf162(h0, h1);
            *(bf162*)&g_al[o0] = bf162(l0, l1);
            split1(co[mi][nj][2] * i1, h0, l0);
            split1(co[mi][nj][3] * i1, h1, l1);
            *(bf162*)&g_ah[o1] = bf162(h0, h1);
            *(bf162*)&g_al[o1] = bf162(l0, l1);
        }
    }
    (void)dummy;
}

// ---------------------------------------------------------------------------
// Launch
// ---------------------------------------------------------------------------
extern "C" void kernel_launch(void* const* d_in, const int* in_sizes, int n_in,
                              void* d_out, int out_size) {
    const float* x  = (const float*)d_in[0];
    const float* Wq = (const float*)d_in[2];
    const float* Wk = (const float*)d_in[3];
    const float* Wv = (const float*)d_in[4];
    const float* Wo = (const float*)d_in[5];
    float* out = (float*)d_out;

    void *p_qo, *p_ko, *p_vo;
    void *p_xh, *p_xl, *p_wqh, *p_wql, *p_wkh, *p_wkl, *p_wvh, *p_wvl, *p_woh, *p_wol;
    void *p_ah, *p_al;
    cudaGetSymbolAddress(&p_qo, g_qo);
    cudaGetSymbolAddress(&p_ko, g_ko);
    cudaGetSymbolAddress(&p_vo, g_vo);
    cudaGetSymbolAddress(&p_xh, g_xh);   cudaGetSymbolAddress(&p_xl, g_xl);
    cudaGetSymbolAddress(&p_wqh, g_wqh); cudaGetSymbolAddress(&p_wql, g_wql);
    cudaGetSymbolAddress(&p_wkh, g_wkh); cudaGetSymbolAddress(&p_wkl, g_wkl);
    cudaGetSymbolAddress(&p_wvh, g_wvh); cudaGetSymbolAddress(&p_wvl, g_wvl);
    cudaGetSymbolAddress(&p_woh, g_woh); cudaGetSymbolAddress(&p_wol, g_wol);
    cudaGetSymbolAddress(&p_ah, g_ah);   cudaGetSymbolAddress(&p_al, g_al);

    cudaFuncSetAttribute(flash_mma, cudaFuncAttributeMaxDynamicSharedMemorySize,
                         (int)sizeof(FlashSmem2));

    // Split inputs to bf16 hi/lo planes
    split_kernel<<<8192, 256>>>(x,  (bf16*)p_xh,  (bf16*)p_xl,  B_ * T_ * HID / 4);
    split_kernel<<<4096, 256>>>(Wq, (bf16*)p_wqh, (bf16*)p_wql, HID * HID / 4);
    split_kernel<<<1024, 256>>>(Wk, (bf16*)p_wkh, (bf16*)p_wkl, NKV * HD * HID / 4);
    split_kernel<<<1024, 256>>>(Wv, (bf16*)p_wvh, (bf16*)p_wvl, NKV * HD * HID / 4);
    split_kernel<<<4096, 256>>>(Wo, (bf16*)p_woh, (bf16*)p_wol, HID * HID / 4);

    // QKV projections
    gemm_bf<<<dim3(16, 32), 256>>>((bf16*)p_xh, (bf16*)p_xl, (bf16*)p_wqh, (bf16*)p_wql,
                                   (float*)p_qo, B_ * T_, NH * HD, HID);
    gemm_bf<<<dim3(4, 32), 256>>>((bf16*)p_xh, (bf16*)p_xl, (bf16*)p_wkh, (bf16*)p_wkl,
                                  (float*)p_ko, B_ * T_, NKV * HD, HID);
    gemm_bf<<<dim3(4, 32), 256>>>((bf16*)p_xh, (bf16*)p_xl, (bf16*)p_wvh, (bf16*)p_wvl,
                                  (float*)p_vo, B_ * T_, NKV * HD, HID);

    // RoPE + V transpose into bf16 planes
    rope_q_kernel<<<(B_ * T_ * NH * 64) / 256, 256>>>();
    rope_k_kernel<<<(B_ * T_ * NKV * 64) / 256, 256>>>();
    vt_kernel<<<dim3(T_ / 32, HD / 32, B_ * NKV), dim3(32, 8)>>>();

    // Flash attention (writes attn hi/lo planes)
    flash_mma<<<dim3(T_ / 128, NH, B_), 256, sizeof(FlashSmem2)>>>(nullptr);

    // Output projection
    gemm_bf<<<dim3(16, 32), 256>>>((bf16*)p_ah, (bf16*)p_al, (bf16*)p_woh, (bf16*)p_wol,
                                   out, B_ * T_, HID, HID);
}

// round 10
// speedup vs baseline: 2.7867x; 1.4434x over previous
#include <cuda_runtime.h>
#include <cuda_bf16.h>
#include <cuda_fp16.h>
#include <math.h>
#include <cstdint>

#define B_   2
#define T_   2048
#define HID  2048
#define NH   16
#define NKV  4
#define HD   128

typedef __nv_bfloat16 bf16;
typedef __nv_bfloat162 bf162;

// ---------------------------------------------------------------------------
// Global scratch
// ---------------------------------------------------------------------------
__device__ __align__(256) float g_qo[(size_t)B_ * T_ * NH * HD];
__device__ __align__(256) float g_ko[(size_t)B_ * T_ * NKV * HD];
__device__ __align__(256) float g_vo[(size_t)B_ * T_ * NKV * HD];

__device__ __align__(256) bf16 g_xh[(size_t)B_ * T_ * HID];
__device__ __align__(256) bf16 g_xl[(size_t)B_ * T_ * HID];
__device__ __align__(256) bf16 g_wqh[(size_t)HID * HID];
__device__ __align__(256) bf16 g_wql[(size_t)HID * HID];
__device__ __align__(256) bf16 g_wkh[(size_t)NKV * HD * HID];
__device__ __align__(256) bf16 g_wkl[(size_t)NKV * HD * HID];
__device__ __align__(256) bf16 g_wvh[(size_t)NKV * HD * HID];
__device__ __align__(256) bf16 g_wvl[(size_t)NKV * HD * HID];
__device__ __align__(256) __half g_wof[(size_t)HID * HID];      // Wo single fp16

__device__ __align__(256) bf16 g_qph[(size_t)B_ * NH * T_ * HD];
__device__ __align__(256) bf16 g_qpl[(size_t)B_ * NH * T_ * HD];
__device__ __align__(256) bf16 g_kph[(size_t)B_ * NKV * T_ * HD];
__device__ __align__(256) bf16 g_kpl[(size_t)B_ * NKV * T_ * HD];
__device__ __align__(256) __half g_vtf[(size_t)B_ * NKV * HD * T_];  // V^T fp16
__device__ __align__(256) __half g_ah[(size_t)B_ * T_ * HID];   // attn hi fp16
__device__ __align__(256) __half g_al[(size_t)B_ * T_ * HID];   // attn lo fp16

// ---------------------------------------------------------------------------
// Helpers
// ---------------------------------------------------------------------------
__device__ __forceinline__ uint32_t smem_u32(const void* p) {
    uint32_t a;
    asm("{ .reg .u64 t; cvta.to.shared.u64 t, %1; cvt.u32.u64 %0, t; }"
        : "=r"(a) : "l"(p));
    return a;
}

#define CP_ASYNC16(dst, src) \
    asm volatile("cp.async.cg.shared.global [%0], [%1], 16;" :: "r"(dst), "l"(src))
#define CP_COMMIT() asm volatile("cp.async.commit_group;" ::: "memory")
#define CP_WAIT0()  asm volatile("cp.async.wait_group 0;" ::: "memory")
#define CP_WAIT1()  asm volatile("cp.async.wait_group 1;" ::: "memory")

__device__ __forceinline__ void mma_bf16(float* c, const uint32_t* a, const uint32_t* b) {
    asm volatile(
        "mma.sync.aligned.m16n8k16.row.col.f32.bf16.bf16.f32 "
        "{%0,%1,%2,%3}, {%4,%5,%6,%7}, {%8,%9}, {%0,%1,%2,%3};"
        : "+f"(c[0]), "+f"(c[1]), "+f"(c[2]), "+f"(c[3])
        : "r"(a[0]), "r"(a[1]), "r"(a[2]), "r"(a[3]), "r"(b[0]), "r"(b[1]));
}

__device__ __forceinline__ void mma_f16(float* c, const uint32_t* a, const uint32_t* b) {
    asm volatile(
        "mma.sync.aligned.m16n8k16.row.col.f32.f16.f16.f32 "
        "{%0,%1,%2,%3}, {%4,%5,%6,%7}, {%8,%9}, {%0,%1,%2,%3};"
        : "+f"(c[0]), "+f"(c[1]), "+f"(c[2]), "+f"(c[3])
        : "r"(a[0]), "r"(a[1]), "r"(a[2]), "r"(a[3]), "r"(b[0]), "r"(b[1]));
}

__device__ __forceinline__ void split1(float v, bf16& h, bf16& l) {
    h = __float2bfloat16(v);
    l = __float2bfloat16(v - __bfloat162float(h));
}
__device__ __forceinline__ void split1h(float v, __half& h, __half& l) {
    h = __float2half_rn(v);
    l = __float2half_rn(v - __half2float(h));
}
__device__ __forceinline__ uint32_t h2pack(float a, float b) {
    __half2 h = __floats2half2_rn(a, b);
    return *(uint32_t*)&h;
}

// ---------------------------------------------------------------------------
// Split passes
// ---------------------------------------------------------------------------
__global__ void split_kernel(const float* __restrict__ in, bf16* __restrict__ oh,
                             bf16* __restrict__ ol, int n4) {
    int i = blockIdx.x * 256 + threadIdx.x;
    if (i >= n4) return;
    float4 v = ((const float4*)in)[i];
    bf16 h0, l0, h1, l1, h2, l2, h3, l3;
    split1(v.x, h0, l0); split1(v.y, h1, l1);
    split1(v.z, h2, l2); split1(v.w, h3, l3);
    ((bf162*)oh)[2 * i]     = bf162(h0, h1);
    ((bf162*)oh)[2 * i + 1] = bf162(h2, h3);
    ((bf162*)ol)[2 * i]     = bf162(l0, l1);
    ((bf162*)ol)[2 * i + 1] = bf162(l2, l3);
}

__global__ void splitf_kernel(const float* __restrict__ in, __half* __restrict__ o, int n4) {
    int i = blockIdx.x * 256 + threadIdx.x;
    if (i >= n4) return;
    float4 v = ((const float4*)in)[i];
    ((__half2*)o)[2 * i]     = __floats2half2_rn(v.x, v.y);
    ((__half2*)o)[2 * i + 1] = __floats2half2_rn(v.z, v.w);
}

// ---------------------------------------------------------------------------
// GEMM NT bf16x3 (unchanged from R8): C = A @ B^T
// ---------------------------------------------------------------------------
#define GSTR 12
#define GPLANE (128 * GSTR)

__global__ __launch_bounds__(256) void gemm_bf(const bf16* __restrict__ Ah,
                                               const bf16* __restrict__ Al,
                                               const bf16* __restrict__ Bh,
                                               const bf16* __restrict__ Bl,
                                               float* __restrict__ C,
                                               int M, int N_, int K) {
    __shared__ __align__(16) uint32_t sm[2][4][GPLANE];
    const int tid = threadIdx.x;
    const int lane = tid & 31, wid = tid >> 5;
    const int g = lane >> 2, tg = lane & 3;
    const int m0 = blockIdx.y * 128, n0 = blockIdx.x * 128;
    const int mw = (wid >> 2) * 64, nw = (wid & 3) * 32;

    float acc[4][4][4];
#pragma unroll
    for (int mi = 0; mi < 4; ++mi)
#pragma unroll
        for (int nj = 0; nj < 4; ++nj)
#pragma unroll
            for (int r = 0; r < 4; ++r) acc[mi][nj][r] = 0.f;

    const int rr = tid >> 1;
    const int hc = (tid & 1) * 8;
    const bf16* src[4] = {
        Ah + (size_t)(m0 + rr) * K + hc, Al + (size_t)(m0 + rr) * K + hc,
        Bh + (size_t)(n0 + rr) * K + hc, Bl + (size_t)(n0 + rr) * K + hc };
    uint32_t dst0[4];
#pragma unroll
    for (int p = 0; p < 4; ++p)
        dst0[p] = smem_u32(&sm[0][p][rr * GSTR + (tid & 1) * 4]);
    const uint32_t bufB = 4 * GPLANE * 4;

#pragma unroll
    for (int p = 0; p < 4; ++p) CP_ASYNC16(dst0[p], src[p]);
    CP_COMMIT();

    const int nkt = K >> 4;
    for (int kt = 0; kt < nkt; ++kt) {
        CP_WAIT0();
        __syncthreads();
        if (kt + 1 < nkt) {
            const int k0 = (kt + 1) << 4;
            const uint32_t bo = ((kt + 1) & 1) * bufB;
#pragma unroll
            for (int p = 0; p < 4; ++p) CP_ASYNC16(dst0[p] + bo, src[p] + k0);
            CP_COMMIT();
        }
        const uint32_t (*cur)[GPLANE] = sm[kt & 1];

        uint32_t ah[4][4], al[4][4], bh[4][2], bl[4][2];
#pragma unroll
        for (int mi = 0; mi < 4; ++mi) {
            int base = (mw + mi * 16 + g) * GSTR + tg;
            ah[mi][0] = cur[0][base];      ah[mi][1] = cur[0][base + 8 * GSTR];
            ah[mi][2] = cur[0][base + 4];  ah[mi][3] = cur[0][base + 8 * GSTR + 4];
            al[mi][0] = cur[1][base];      al[mi][1] = cur[1][base + 8 * GSTR];
            al[mi][2] = cur[1][base + 4];  al[mi][3] = cur[1][base + 8 * GSTR + 4];
        }
#pragma unroll
        for (int nj = 0; nj < 4; ++nj) {
            int base = (nw + nj * 8 + g) * GSTR + tg;
            bh[nj][0] = cur[2][base]; bh[nj][1] = cur[2][base + 4];
            bl[nj][0] = cur[3][base]; bl[nj][1] = cur[3][base + 4];
        }
#pragma unroll
        for (int mi = 0; mi < 4; ++mi)
#pragma unroll
            for (int nj = 0; nj < 4; ++nj) {
                mma_bf16(acc[mi][nj], ah[mi], bh[nj]);
                mma_bf16(acc[mi][nj], ah[mi], bl[nj]);
                mma_bf16(acc[mi][nj], al[mi], bh[nj]);
            }
    }

#pragma unroll
    for (int mi = 0; mi < 4; ++mi) {
#pragma unroll
        for (int nj = 0; nj < 4; ++nj) {
            int row = m0 + mw + mi * 16 + g;
            int col = n0 + nw + nj * 8 + tg * 2;
            *(float2*)(C + (size_t)row * N_ + col) =
                make_float2(acc[mi][nj][0], acc[mi][nj][1]);
            *(float2*)(C + (size_t)(row + 8) * N_ + col) =
                make_float2(acc[mi][nj][2], acc[mi][nj][3]);
        }
    }
}

// ---------------------------------------------------------------------------
// GEMM NT fp16 2-pass: C = (Ah+Al) @ B^T   (A split fp16x2, B single fp16)
// ---------------------------------------------------------------------------
__global__ __launch_bounds__(256) void gemm_f16(const __half* __restrict__ Ah,
                                                const __half* __restrict__ Al,
                                                const __half* __restrict__ Bf,
                                                float* __restrict__ C,
                                                int M, int N_, int K) {
    __shared__ __align__(16) uint32_t sm[2][3][GPLANE];
    const int tid = threadIdx.x;
    const int lane = tid & 31, wid = tid >> 5;
    const int g = lane >> 2, tg = lane & 3;
    const int m0 = blockIdx.y * 128, n0 = blockIdx.x * 128;
    const int mw = (wid >> 2) * 64, nw = (wid & 3) * 32;

    float acc[4][4][4];
#pragma unroll
    for (int mi = 0; mi < 4; ++mi)
#pragma unroll
        for (int nj = 0; nj < 4; ++nj)
#pragma unroll
            for (int r = 0; r < 4; ++r) acc[mi][nj][r] = 0.f;

    const int rr = tid >> 1;
    const int hc = (tid & 1) * 8;
    const __half* src[3] = {
        Ah + (size_t)(m0 + rr) * K + hc, Al + (size_t)(m0 + rr) * K + hc,
        Bf + (size_t)(n0 + rr) * K + hc };
    uint32_t dst0[3];
#pragma unroll
    for (int p = 0; p < 3; ++p)
        dst0[p] = smem_u32(&sm[0][p][rr * GSTR + (tid & 1) * 4]);
    const uint32_t bufB = 3 * GPLANE * 4;

#pragma unroll
    for (int p = 0; p < 3; ++p) CP_ASYNC16(dst0[p], src[p]);
    CP_COMMIT();

    const int nkt = K >> 4;
    for (int kt = 0; kt < nkt; ++kt) {
        CP_WAIT0();
        __syncthreads();
        if (kt + 1 < nkt) {
            const int k0 = (kt + 1) << 4;
            const uint32_t bo = ((kt + 1) & 1) * bufB;
#pragma unroll
            for (int p = 0; p < 3; ++p) CP_ASYNC16(dst0[p] + bo, src[p] + k0);
            CP_COMMIT();
        }
        const uint32_t (*cur)[GPLANE] = sm[kt & 1];

        uint32_t ah[4][4], al[4][4], bh[4][2];
#pragma unroll
        for (int mi = 0; mi < 4; ++mi) {
            int base = (mw + mi * 16 + g) * GSTR + tg;
            ah[mi][0] = cur[0][base];      ah[mi][1] = cur[0][base + 8 * GSTR];
            ah[mi][2] = cur[0][base + 4];  ah[mi][3] = cur[0][base + 8 * GSTR + 4];
            al[mi][0] = cur[1][base];      al[mi][1] = cur[1][base + 8 * GSTR];
            al[mi][2] = cur[1][base + 4];  al[mi][3] = cur[1][base + 8 * GSTR + 4];
        }
#pragma unroll
        for (int nj = 0; nj < 4; ++nj) {
            int base = (nw + nj * 8 + g) * GSTR + tg;
            bh[nj][0] = cur[2][base]; bh[nj][1] = cur[2][base + 4];
        }
#pragma unroll
        for (int mi = 0; mi < 4; ++mi)
#pragma unroll
            for (int nj = 0; nj < 4; ++nj) {
                mma_f16(acc[mi][nj], ah[mi], bh[nj]);
                mma_f16(acc[mi][nj], al[mi], bh[nj]);
            }
    }

#pragma unroll
    for (int mi = 0; mi < 4; ++mi) {
#pragma unroll
        for (int nj = 0; nj < 4; ++nj) {
            int row = m0 + mw + mi * 16 + g;
            int col = n0 + nw + nj * 8 + tg * 2;
            *(float2*)(C + (size_t)row * N_ + col) =
                make_float2(acc[mi][nj][0], acc[mi][nj][1]);
            *(float2*)(C + (size_t)(row + 8) * N_ + col) =
                make_float2(acc[mi][nj][2], acc[mi][nj][3]);
        }
    }
}

// ---------------------------------------------------------------------------
// RoPE -> bf16 hi/lo planes (unchanged)
// ---------------------------------------------------------------------------
__global__ void rope_q_kernel() {
    int idx = blockIdx.x * 256 + threadIdx.x;
    int j = idx & 63;
    int h = (idx >> 6) & (NH - 1);
    int t = (idx >> 10) & (T_ - 1);
    int b = idx >> 21;
    float inv = powf(10000.0f, -(float)j / 64.0f);
    float s, c;
    sincosf((float)t * inv, &s, &c);
    const float scale = 0.08838834764831845f;
    const float* src = g_qo + (size_t)(b * T_ + t) * (NH * HD) + h * HD;
    float x1 = src[j], x2 = src[j + 64];
    float y1 = (x1 * c - x2 * s) * scale;
    float y2 = (x2 * c + x1 * s) * scale;
    size_t o = ((size_t)(b * NH + h) * T_ + t) * HD;
    bf16 hh, ll;
    split1(y1, hh, ll); g_qph[o + j] = hh;      g_qpl[o + j] = ll;
    split1(y2, hh, ll); g_qph[o + j + 64] = hh; g_qpl[o + j + 64] = ll;
}

__global__ void rope_k_kernel() {
    int idx = blockIdx.x * 256 + threadIdx.x;
    int j  = idx & 63;
    int kh = (idx >> 6) & (NKV - 1);
    int t  = (idx >> 8) & (T_ - 1);
    int b  = idx >> 19;
    float inv = powf(10000.0f, -(float)j / 64.0f);
    float s, c;
    sincosf((float)t * inv, &s, &c);
    const float* src = g_ko + (size_t)(b * T_ + t) * (NKV * HD) + kh * HD;
    float x1 = src[j], x2 = src[j + 64];
    float y1 = x1 * c - x2 * s;
    float y2 = x2 * c + x1 * s;
    size_t o = ((size_t)(b * NKV + kh) * T_ + t) * HD;
    bf16 hh, ll;
    split1(y1, hh, ll); g_kph[o + j] = hh;      g_kpl[o + j] = ll;
    split1(y2, hh, ll); g_kph[o + j + 64] = hh; g_kpl[o + j + 64] = ll;
}

// ---------------------------------------------------------------------------
// V transpose: fp32 [b*T+t][kh*128+d] -> single fp16 [(b,kh)*128+d][T]
// ---------------------------------------------------------------------------
__global__ void vt_kernel() {
    __shared__ float tl[32][33];
    int tx = threadIdx.x, ty = threadIdx.y;
    int t0 = blockIdx.x * 32, d0 = blockIdx.y * 32, bk = blockIdx.z;
    int b = bk >> 2, kh = bk & 3;
#pragma unroll
    for (int i = 0; i < 4; ++i)
        tl[ty + 8 * i][tx] =
            g_vo[(size_t)(b * T_ + t0 + ty + 8 * i) * (NKV * HD) + kh * HD + d0 + tx];
    __syncthreads();
#pragma unroll
    for (int i = 0; i < 4; ++i) {
        int dd = ty + 8 * i;
        g_vtf[((size_t)bk * HD + d0 + dd) * T_ + t0 + tx] = __float2half_rn(tl[tx][dd]);
    }
}

// ---------------------------------------------------------------------------
// Flash attention FA2-style: register softmax, P in regs, PV fp16 1-pass,
// double-buffered cp.async K/V. 8 warps x 16 q-rows, BN=64.
// ---------------------------------------------------------------------------
#define KSTR 68   // u32 per Q/K row (272 B)
#define VSTR 36   // u32 per V row (144 B)

struct FlashSmem3 {
    uint32_t Qh[128 * KSTR], Ql[128 * KSTR];
    uint32_t Kh[2][64 * KSTR], Kl[2][64 * KSTR];
    uint32_t Vf[2][128 * VSTR];
};
static_assert(sizeof(FlashSmem3) <= 227 * 1024, "smem too big");

__global__ __launch_bounds__(256, 1) void flash_mma(float* dummy) {
    extern __shared__ unsigned char smraw[];
    FlashSmem3& sm = *reinterpret_cast<FlashSmem3*>(smraw);
    const int tid = threadIdx.x;
    const int lane = tid & 31, w = tid >> 5;
    const int g = lane >> 2, tg = lane & 3;
    const int b = blockIdx.z, h = blockIdx.y;
    const int q0 = blockIdx.x * 128;
    const int kh = h >> 2;

    const bf16* Qhg = g_qph + ((size_t)(b * NH + h) * T_ + q0) * HD;
    const bf16* Qlg = g_qpl + ((size_t)(b * NH + h) * T_ + q0) * HD;
    const bf16* Khg = g_kph + (size_t)(b * NKV + kh) * T_ * HD;
    const bf16* Klg = g_kpl + (size_t)(b * NKV + kh) * T_ * HD;
    const __half* Vfg = g_vtf + (size_t)(b * NKV + kh) * HD * T_;

    // Q tile load (plain vector loads)
    for (int s = tid; s < 128 * 16; s += 256) {
        int row = s >> 4, c16 = s & 15;
        *(uint4*)&sm.Qh[row * KSTR + c16 * 4] = *(const uint4*)(Qhg + (size_t)row * HD + c16 * 8);
        *(uint4*)&sm.Ql[row * KSTR + c16 * 4] = *(const uint4*)(Qlg + (size_t)row * HD + c16 * 8);
    }

    float o[16][4];
#pragma unroll
    for (int t = 0; t < 16; ++t)
#pragma unroll
        for (int r = 0; r < 4; ++r) o[t][r] = 0.f;
    float m0 = -1e30f, m1 = -1e30f, l0 = 0.f, l1 = 0.f;

    const int row0 = q0 + w * 16 + g;
    const int row1 = row0 + 8;
    const int ntiles = (q0 >> 6) + 2;

    // issue loads for tile kt into buffer kt&1
    auto issue_tile = [&](int kt) {
        const int k0 = kt * 64;
        const int bi = kt & 1;
        const uint32_t khb = smem_u32(sm.Kh[bi]);
        const uint32_t klb = smem_u32(sm.Kl[bi]);
        const uint32_t vfb = smem_u32(sm.Vf[bi]);
        for (int s = tid; s < 64 * 16; s += 256) {
            int row = s >> 4, c16 = s & 15;
            CP_ASYNC16(khb + (row * KSTR + c16 * 4) * 4,
                       Khg + (size_t)(k0 + row) * HD + c16 * 8);
            CP_ASYNC16(klb + (row * KSTR + c16 * 4) * 4,
                       Klg + (size_t)(k0 + row) * HD + c16 * 8);
        }
        for (int s = tid; s < 128 * 8; s += 256) {
            int d = s >> 3, c8 = s & 7;
            CP_ASYNC16(vfb + (d * VSTR + c8 * 4) * 4,
                       Vfg + (size_t)d * T_ + k0 + c8 * 8);
        }
        CP_COMMIT();
    };

    issue_tile(0);

    for (int kt = 0; kt < ntiles; ++kt) {
        const int k0 = kt * 64;
        if (kt + 1 < ntiles) { issue_tile(kt + 1); CP_WAIT1(); }
        else                 { CP_WAIT0(); }
        __syncthreads();

        const uint32_t* KhB = sm.Kh[kt & 1];
        const uint32_t* KlB = sm.Kl[kt & 1];
        const uint32_t* VfB = sm.Vf[kt & 1];

        // ---- S = Q K^T (bf16x3), warp tile 16x64 ----
        float cs[8][4];
#pragma unroll
        for (int nj = 0; nj < 8; ++nj)
#pragma unroll
            for (int r = 0; r < 4; ++r) cs[nj][r] = 0.f;

#pragma unroll
        for (int kf = 0; kf < 8; ++kf) {
            uint32_t qh[4], ql[4];
            int ab = (w * 16 + g) * KSTR + kf * 8 + tg;
            qh[0] = sm.Qh[ab];            qh[1] = sm.Qh[ab + 8 * KSTR];
            qh[2] = sm.Qh[ab + 4];        qh[3] = sm.Qh[ab + 8 * KSTR + 4];
            ql[0] = sm.Ql[ab];            ql[1] = sm.Ql[ab + 8 * KSTR];
            ql[2] = sm.Ql[ab + 4];        ql[3] = sm.Ql[ab + 8 * KSTR + 4];
#pragma unroll
            for (int nj = 0; nj < 8; ++nj) {
                int bb = (nj * 8 + g) * KSTR + kf * 8 + tg;
                uint32_t k2h[2] = { KhB[bb], KhB[bb + 4] };
                uint32_t k2l[2] = { KlB[bb], KlB[bb + 4] };
                mma_bf16(cs[nj], qh, k2h);
                mma_bf16(cs[nj], qh, k2l);
                mma_bf16(cs[nj], ql, k2h);
            }
        }

        // ---- causal mask (registers) ----
#pragma unroll
        for (int nj = 0; nj < 8; ++nj) {
            int c0 = k0 + nj * 8 + tg * 2, c1 = c0 + 1;
            cs[nj][0] = (c0 <= row0) ? cs[nj][0] : -1e30f;
            cs[nj][1] = (c1 <= row0) ? cs[nj][1] : -1e30f;
            cs[nj][2] = (c0 <= row1) ? cs[nj][2] : -1e30f;
            cs[nj][3] = (c1 <= row1) ? cs[nj][3] : -1e30f;
        }

        // ---- register softmax (rows live within warp; reduce over tg) ----
        float mx0 = -1e30f, mx1 = -1e30f;
#pragma unroll
        for (int nj = 0; nj < 8; ++nj) {
            mx0 = fmaxf(mx0, fmaxf(cs[nj][0], cs[nj][1]));
            mx1 = fmaxf(mx1, fmaxf(cs[nj][2], cs[nj][3]));
        }
        mx0 = fmaxf(mx0, __shfl_xor_sync(0xffffffffu, mx0, 1));
        mx0 = fmaxf(mx0, __shfl_xor_sync(0xffffffffu, mx0, 2));
        mx1 = fmaxf(mx1, __shfl_xor_sync(0xffffffffu, mx1, 1));
        mx1 = fmaxf(mx1, __shfl_xor_sync(0xffffffffu, mx1, 2));

        float mn0 = fmaxf(m0, mx0), mn1 = fmaxf(m1, mx1);
        float al0 = __expf(m0 - mn0), al1 = __expf(m1 - mn1);
        float s0 = 0.f, s1 = 0.f;
#pragma unroll
        for (int nj = 0; nj < 8; ++nj) {
            cs[nj][0] = __expf(cs[nj][0] - mn0);
            cs[nj][1] = __expf(cs[nj][1] - mn0);
            cs[nj][2] = __expf(cs[nj][2] - mn1);
            cs[nj][3] = __expf(cs[nj][3] - mn1);
            s0 += cs[nj][0] + cs[nj][1];
            s1 += cs[nj][2] + cs[nj][3];
        }
        s0 += __shfl_xor_sync(0xffffffffu, s0, 1);
        s0 += __shfl_xor_sync(0xffffffffu, s0, 2);
        s1 += __shfl_xor_sync(0xffffffffu, s1, 1);
        s1 += __shfl_xor_sync(0xffffffffu, s1, 2);
        l0 = l0 * al0 + s0;
        l1 = l1 * al1 + s1;
        m0 = mn0; m1 = mn1;

        // ---- rescale O ----
#pragma unroll
        for (int t = 0; t < 16; ++t) {
            o[t][0] *= al0; o[t][1] *= al0;
            o[t][2] *= al1; o[t][3] *= al1;
        }

        // ---- O += P V  (fp16 single-pass; P packed from registers) ----
#pragma unroll
        for (int kf = 0; kf < 4; ++kf) {
            uint32_t pa[4];
            pa[0] = h2pack(cs[2 * kf][0],     cs[2 * kf][1]);
            pa[1] = h2pack(cs[2 * kf][2],     cs[2 * kf][3]);
            pa[2] = h2pack(cs[2 * kf + 1][0], cs[2 * kf + 1][1]);
            pa[3] = h2pack(cs[2 * kf + 1][2], cs[2 * kf + 1][3]);
#pragma unroll
            for (int nj = 0; nj < 16; ++nj) {
                int bb = (nj * 8 + g) * VSTR + kf * 8 + tg;
                uint32_t bv[2] = { VfB[bb], VfB[bb + 4] };
                mma_f16(o[nj], pa, bv);
            }
        }
        __syncthreads();   // protect buffers before next iteration's issue
    }

    // ---- epilogue: normalize, split to fp16 hi/lo attn planes ----
    float i0 = 1.0f / l0, i1 = 1.0f / l1;
    int r0 = q0 + w * 16 + g, r1 = r0 + 8;
#pragma unroll
    for (int nj = 0; nj < 16; ++nj) {
        int col = nj * 8 + tg * 2;
        size_t o0 = (size_t)(b * T_ + r0) * HID + h * HD + col;
        size_t o1 = (size_t)(b * T_ + r1) * HID + h * HD + col;
        __half h0, lo0, h1, lo1;
        split1h(o[nj][0] * i0, h0, lo0);
        split1h(o[nj][1] * i0, h1, lo1);
        *(__half2*)&g_ah[o0] = __halves2half2(h0, h1);
        *(__half2*)&g_al[o0] = __halves2half2(lo0, lo1);
        split1h(o[nj][2] * i1, h0, lo0);
        split1h(o[nj][3] * i1, h1, lo1);
        *(__half2*)&g_ah[o1] = __halves2half2(h0, h1);
        *(__half2*)&g_al[o1] = __halves2half2(lo0, lo1);
    }
    (void)dummy;
}

// ---------------------------------------------------------------------------
// Launch
// ---------------------------------------------------------------------------
extern "C" void kernel_launch(void* const* d_in, const int* in_sizes, int n_in,
                              void* d_out, int out_size) {
    const float* x  = (const float*)d_in[0];
    const float* Wq = (const float*)d_in[2];
    const float* Wk = (const float*)d_in[3];
    const float* Wv = (const float*)d_in[4];
    const float* Wo = (const float*)d_in[5];
    float* out = (float*)d_out;

    void *p_qo, *p_ko, *p_vo;
    void *p_xh, *p_xl, *p_wqh, *p_wql, *p_wkh, *p_wkl, *p_wvh, *p_wvl, *p_wof;
    void *p_ah, *p_al;
    cudaGetSymbolAddress(&p_qo, g_qo);
    cudaGetSymbolAddress(&p_ko, g_ko);
    cudaGetSymbolAddress(&p_vo, g_vo);
    cudaGetSymbolAddress(&p_xh, g_xh);   cudaGetSymbolAddress(&p_xl, g_xl);
    cudaGetSymbolAddress(&p_wqh, g_wqh); cudaGetSymbolAddress(&p_wql, g_wql);
    cudaGetSymbolAddress(&p_wkh, g_wkh); cudaGetSymbolAddress(&p_wkl, g_wkl);
    cudaGetSymbolAddress(&p_wvh, g_wvh); cudaGetSymbolAddress(&p_wvl, g_wvl);
    cudaGetSymbolAddress(&p_wof, g_wof);
    cudaGetSymbolAddress(&p_ah, g_ah);   cudaGetSymbolAddress(&p_al, g_al);

    cudaFuncSetAttribute(flash_mma, cudaFuncAttributeMaxDynamicSharedMemorySize,
                         (int)sizeof(FlashSmem3));

    // Splits
    split_kernel<<<8192, 256>>>(x,  (bf16*)p_xh,  (bf16*)p_xl,  B_ * T_ * HID / 4);
    split_kernel<<<4096, 256>>>(Wq, (bf16*)p_wqh, (bf16*)p_wql, HID * HID / 4);
    split_kernel<<<1024, 256>>>(Wk, (bf16*)p_wkh, (bf16*)p_wkl, NKV * HD * HID / 4);
    split_kernel<<<1024, 256>>>(Wv, (bf16*)p_wvh, (bf16*)p_wvl, NKV * HD * HID / 4);
    splitf_kernel<<<4096, 256>>>(Wo, (__half*)p_wof, HID * HID / 4);

    // QKV projections (bf16x3)
    gemm_bf<<<dim3(16, 32), 256>>>((bf16*)p_xh, (bf16*)p_xl, (bf16*)p_wqh, (bf16*)p_wql,
                                   (float*)p_qo, B_ * T_, NH * HD, HID);
    gemm_bf<<<dim3(4, 32), 256>>>((bf16*)p_xh, (bf16*)p_xl, (bf16*)p_wkh, (bf16*)p_wkl,
                                  (float*)p_ko, B_ * T_, NKV * HD, HID);
    gemm_bf<<<dim3(4, 32), 256>>>((bf16*)p_xh, (bf16*)p_xl, (bf16*)p_wvh, (bf16*)p_wvl,
                                  (float*)p_vo, B_ * T_, NKV * HD, HID);

    // RoPE + V transpose
    rope_q_kernel<<<(B_ * T_ * NH * 64) / 256, 256>>>();
    rope_k_kernel<<<(B_ * T_ * NKV * 64) / 256, 256>>>();
    vt_kernel<<<dim3(T_ / 32, HD / 32, B_ * NKV), dim3(32, 8)>>>();

    // Flash attention
    flash_mma<<<dim3(T_ / 128, NH, B_), 256, sizeof(FlashSmem3)>>>(nullptr);

    // Output projection (fp16 2-pass)
    gemm_f16<<<dim3(16, 32), 256>>>((const __half*)p_ah, (const __half*)p_al,
                                    (const __half*)p_wof, out, B_ * T_, HID, HID);
}

// round 13
// speedup vs baseline: 3.3795x; 1.2127x over previous
#include <cuda_runtime.h>
#include <cuda_bf16.h>
#include <cuda_fp16.h>
#include <math.h>
#include <cstdint>

#define B_   2
#define T_   2048
#define HID  2048
#define NH   16
#define NKV  4
#define HD   128

// ---------------------------------------------------------------------------
// Global scratch (all fp16 planes now)
// ---------------------------------------------------------------------------
__device__ __align__(256) float g_qo[(size_t)B_ * T_ * NH * HD];
__device__ __align__(256) float g_ko[(size_t)B_ * T_ * NKV * HD];
__device__ __align__(256) float g_vo[(size_t)B_ * T_ * NKV * HD];

__device__ __align__(256) __half g_xh[(size_t)B_ * T_ * HID];
__device__ __align__(256) __half g_xl[(size_t)B_ * T_ * HID];
__device__ __align__(256) __half g_wqf[(size_t)HID * HID];
__device__ __align__(256) __half g_wkf[(size_t)NKV * HD * HID];
__device__ __align__(256) __half g_wvf[(size_t)NKV * HD * HID];
__device__ __align__(256) __half g_wof[(size_t)HID * HID];

__device__ __align__(256) __half g_qph[(size_t)B_ * NH * T_ * HD];   // Q hi
__device__ __align__(256) __half g_qpl[(size_t)B_ * NH * T_ * HD];   // Q lo
__device__ __align__(256) __half g_kpf[(size_t)B_ * NKV * T_ * HD];  // K single
__device__ __align__(256) __half g_vtf[(size_t)B_ * NKV * HD * T_];  // V^T single
__device__ __align__(256) __half g_ah[(size_t)B_ * T_ * HID];        // attn hi
__device__ __align__(256) __half g_al[(size_t)B_ * T_ * HID];        // attn lo

// ---------------------------------------------------------------------------
// Helpers
// ---------------------------------------------------------------------------
__device__ __forceinline__ uint32_t smem_u32(const void* p) {
    uint32_t a;
    asm("{ .reg .u64 t; cvta.to.shared.u64 t, %1; cvt.u32.u64 %0, t; }"
        : "=r"(a) : "l"(p));
    return a;
}

#define CP_ASYNC16(dst, src) \
    asm volatile("cp.async.cg.shared.global [%0], [%1], 16;" :: "r"(dst), "l"(src))
#define CP_COMMIT() asm volatile("cp.async.commit_group;" ::: "memory")
#define CP_WAIT0()  asm volatile("cp.async.wait_group 0;" ::: "memory")
#define CP_WAIT1()  asm volatile("cp.async.wait_group 1;" ::: "memory")

__device__ __forceinline__ void mma_f16(float* c, const uint32_t* a, const uint32_t* b) {
    asm volatile(
        "mma.sync.aligned.m16n8k16.row.col.f32.f16.f16.f32 "
        "{%0,%1,%2,%3}, {%4,%5,%6,%7}, {%8,%9}, {%0,%1,%2,%3};"
        : "+f"(c[0]), "+f"(c[1]), "+f"(c[2]), "+f"(c[3])
        : "r"(a[0]), "r"(a[1]), "r"(a[2]), "r"(a[3]), "r"(b[0]), "r"(b[1]));
}

__device__ __forceinline__ void split1h(float v, __half& h, __half& l) {
    h = __float2half_rn(v);
    l = __float2half_rn(v - __half2float(h));
}
__device__ __forceinline__ uint32_t h2pack(float a, float b) {
    __half2 h = __floats2half2_rn(a, b);
    return *(uint32_t*)&h;
}

// ---------------------------------------------------------------------------
// Split passes
// ---------------------------------------------------------------------------
__global__ void splith_kernel(const float* __restrict__ in, __half* __restrict__ oh,
                              __half* __restrict__ ol, int n4) {
    int i = blockIdx.x * 256 + threadIdx.x;
    if (i >= n4) return;
    float4 v = ((const float4*)in)[i];
    __half h0, l0, h1, l1, h2, l2, h3, l3;
    split1h(v.x, h0, l0); split1h(v.y, h1, l1);
    split1h(v.z, h2, l2); split1h(v.w, h3, l3);
    ((__half2*)oh)[2 * i]     = __halves2half2(h0, h1);
    ((__half2*)oh)[2 * i + 1] = __halves2half2(h2, h3);
    ((__half2*)ol)[2 * i]     = __halves2half2(l0, l1);
    ((__half2*)ol)[2 * i + 1] = __halves2half2(l2, l3);
}

__global__ void splitf_kernel(const float* __restrict__ in, __half* __restrict__ o, int n4) {
    int i = blockIdx.x * 256 + threadIdx.x;
    if (i >= n4) return;
    float4 v = ((const float4*)in)[i];
    ((__half2*)o)[2 * i]     = __floats2half2_rn(v.x, v.y);
    ((__half2*)o)[2 * i + 1] = __floats2half2_rn(v.z, v.w);
}

// ---------------------------------------------------------------------------
// GEMM NT fp16 2-pass: C = (Ah+Al) @ B^T   (A split fp16x2, B single fp16)
// 128x128 tile, BK=16, 8 warps (2m x 4n), cp.async double-buffered.
// ---------------------------------------------------------------------------
#define GSTR 12
#define GPLANE (128 * GSTR)

__global__ __launch_bounds__(256) void gemm_f16(const __half* __restrict__ Ah,
                                                const __half* __restrict__ Al,
                                                const __half* __restrict__ Bf,
                                                float* __restrict__ C,
                                                int M, int N_, int K) {
    __shared__ __align__(16) uint32_t sm[2][3][GPLANE];
    const int tid = threadIdx.x;
    const int lane = tid & 31, wid = tid >> 5;
    const int g = lane >> 2, tg = lane & 3;
    const int m0 = blockIdx.y * 128, n0 = blockIdx.x * 128;
    const int mw = (wid >> 2) * 64, nw = (wid & 3) * 32;

    float acc[4][4][4];
#pragma unroll
    for (int mi = 0; mi < 4; ++mi)
#pragma unroll
        for (int nj = 0; nj < 4; ++nj)
#pragma unroll
            for (int r = 0; r < 4; ++r) acc[mi][nj][r] = 0.f;

    const int rr = tid >> 1;
    const int hc = (tid & 1) * 8;
    const __half* src[3] = {
        Ah + (size_t)(m0 + rr) * K + hc, Al + (size_t)(m0 + rr) * K + hc,
        Bf + (size_t)(n0 + rr) * K + hc };
    uint32_t dst0[3];
#pragma unroll
    for (int p = 0; p < 3; ++p)
        dst0[p] = smem_u32(&sm[0][p][rr * GSTR + (tid & 1) * 4]);
    const uint32_t bufB = 3 * GPLANE * 4;

#pragma unroll
    for (int p = 0; p < 3; ++p) CP_ASYNC16(dst0[p], src[p]);
    CP_COMMIT();

    const int nkt = K >> 4;
    for (int kt = 0; kt < nkt; ++kt) {
        CP_WAIT0();
        __syncthreads();
        if (kt + 1 < nkt) {
            const int k0 = (kt + 1) << 4;
            const uint32_t bo = ((kt + 1) & 1) * bufB;
#pragma unroll
            for (int p = 0; p < 3; ++p) CP_ASYNC16(dst0[p] + bo, src[p] + k0);
            CP_COMMIT();
        }
        const uint32_t (*cur)[GPLANE] = sm[kt & 1];

        uint32_t ah[4][4], al[4][4], bh[4][2];
#pragma unroll
        for (int mi = 0; mi < 4; ++mi) {
            int base = (mw + mi * 16 + g) * GSTR + tg;
            ah[mi][0] = cur[0][base];      ah[mi][1] = cur[0][base + 8 * GSTR];
            ah[mi][2] = cur[0][base + 4];  ah[mi][3] = cur[0][base + 8 * GSTR + 4];
            al[mi][0] = cur[1][base];      al[mi][1] = cur[1][base + 8 * GSTR];
            al[mi][2] = cur[1][base + 4];  al[mi][3] = cur[1][base + 8 * GSTR + 4];
        }
#pragma unroll
        for (int nj = 0; nj < 4; ++nj) {
            int base = (nw + nj * 8 + g) * GSTR + tg;
            bh[nj][0] = cur[2][base]; bh[nj][1] = cur[2][base + 4];
        }
#pragma unroll
        for (int mi = 0; mi < 4; ++mi)
#pragma unroll
            for (int nj = 0; nj < 4; ++nj) {
                mma_f16(acc[mi][nj], ah[mi], bh[nj]);
                mma_f16(acc[mi][nj], al[mi], bh[nj]);
            }
    }

#pragma unroll
    for (int mi = 0; mi < 4; ++mi) {
#pragma unroll
        for (int nj = 0; nj < 4; ++nj) {
            int row = m0 + mw + mi * 16 + g;
            int col = n0 + nw + nj * 8 + tg * 2;
            *(float2*)(C + (size_t)row * N_ + col) =
                make_float2(acc[mi][nj][0], acc[mi][nj][1]);
            *(float2*)(C + (size_t)(row + 8) * N_ + col) =
                make_float2(acc[mi][nj][2], acc[mi][nj][3]);
        }
    }
}

// ---------------------------------------------------------------------------
// RoPE: Q -> fp16 hi/lo planes, K -> single fp16 plane
// ---------------------------------------------------------------------------
__global__ void rope_q_kernel() {
    int idx = blockIdx.x * 256 + threadIdx.x;
    int j = idx & 63;
    int h = (idx >> 6) & (NH - 1);
    int t = (idx >> 10) & (T_ - 1);
    int b = idx >> 21;
    float inv = powf(10000.0f, -(float)j / 64.0f);
    float s, c;
    sincosf((float)t * inv, &s, &c);
    const float scale = 0.08838834764831845f;
    const float* src = g_qo + (size_t)(b * T_ + t) * (NH * HD) + h * HD;
    float x1 = src[j], x2 = src[j + 64];
    float y1 = (x1 * c - x2 * s) * scale;
    float y2 = (x2 * c + x1 * s) * scale;
    size_t o = ((size_t)(b * NH + h) * T_ + t) * HD;
    __half hh, ll;
    split1h(y1, hh, ll); g_qph[o + j] = hh;      g_qpl[o + j] = ll;
    split1h(y2, hh, ll); g_qph[o + j + 64] = hh; g_qpl[o + j + 64] = ll;
}

__global__ void rope_k_kernel() {
    int idx = blockIdx.x * 256 + threadIdx.x;
    int j  = idx & 63;
    int kh = (idx >> 6) & (NKV - 1);
    int t  = (idx >> 8) & (T_ - 1);
    int b  = idx >> 19;
    float inv = powf(10000.0f, -(float)j / 64.0f);
    float s, c;
    sincosf((float)t * inv, &s, &c);
    const float* src = g_ko + (size_t)(b * T_ + t) * (NKV * HD) + kh * HD;
    float x1 = src[j], x2 = src[j + 64];
    size_t o = ((size_t)(b * NKV + kh) * T_ + t) * HD;
    g_kpf[o + j]      = __float2half_rn(x1 * c - x2 * s);
    g_kpf[o + j + 64] = __float2half_rn(x2 * c + x1 * s);
}

// ---------------------------------------------------------------------------
// V transpose: fp32 [b*T+t][kh*128+d] -> single fp16 [(b,kh)*128+d][T]
// ---------------------------------------------------------------------------
__global__ void vt_kernel() {
    __shared__ float tl[32][33];
    int tx = threadIdx.x, ty = threadIdx.y;
    int t0 = blockIdx.x * 32, d0 = blockIdx.y * 32, bk = blockIdx.z;
    int b = bk >> 2, kh = bk & 3;
#pragma unroll
    for (int i = 0; i < 4; ++i)
        tl[ty + 8 * i][tx] =
            g_vo[(size_t)(b * T_ + t0 + ty + 8 * i) * (NKV * HD) + kh * HD + d0 + tx];
    __syncthreads();
#pragma unroll
    for (int i = 0; i < 4; ++i) {
        int dd = ty + 8 * i;
        g_vtf[((size_t)bk * HD + d0 + dd) * T_ + t0 + tx] = __float2half_rn(tl[tx][dd]);
    }
}

// ---------------------------------------------------------------------------
// Flash attention: S fp16 2-pass (Q split x K single), PV fp16 1-pass,
// register softmax, double-buffered cp.async K/V. 8 warps x 16 q-rows, BN=64.
// ---------------------------------------------------------------------------
#define KSTR 68   // u32 per Q/K row (272 B)
#define VSTR 36   // u32 per V row (144 B)

struct FlashSmem4 {
    uint32_t Qh[128 * KSTR], Ql[128 * KSTR];
    uint32_t Kf[2][64 * KSTR];
    uint32_t Vf[2][128 * VSTR];
};
static_assert(sizeof(FlashSmem4) <= 227 * 1024, "smem too big");

__global__ __launch_bounds__(256, 1) void flash_mma(float* dummy) {
    extern __shared__ unsigned char smraw[];
    FlashSmem4& sm = *reinterpret_cast<FlashSmem4*>(smraw);
    const int tid = threadIdx.x;
    const int lane = tid & 31, w = tid >> 5;
    const int g = lane >> 2, tg = lane & 3;
    const int b = blockIdx.z, h = blockIdx.y;
    const int q0 = blockIdx.x * 128;
    const int kh = h >> 2;

    const __half* Qhg = g_qph + ((size_t)(b * NH + h) * T_ + q0) * HD;
    const __half* Qlg = g_qpl + ((size_t)(b * NH + h) * T_ + q0) * HD;
    const __half* Kfg = g_kpf + (size_t)(b * NKV + kh) * T_ * HD;
    const __half* Vfg = g_vtf + (size_t)(b * NKV + kh) * HD * T_;

    // Q tile load
    for (int s = tid; s < 128 * 16; s += 256) {
        int row = s >> 4, c16 = s & 15;
        *(uint4*)&sm.Qh[row * KSTR + c16 * 4] = *(const uint4*)(Qhg + (size_t)row * HD + c16 * 8);
        *(uint4*)&sm.Ql[row * KSTR + c16 * 4] = *(const uint4*)(Qlg + (size_t)row * HD + c16 * 8);
    }

    float o[16][4];
#pragma unroll
    for (int t = 0; t < 16; ++t)
#pragma unroll
        for (int r = 0; r < 4; ++r) o[t][r] = 0.f;
    float m0 = -1e30f, m1 = -1e30f, l0 = 0.f, l1 = 0.f;

    const int row0 = q0 + w * 16 + g;
    const int row1 = row0 + 8;
    const int ntiles = (q0 >> 6) + 2;

    auto issue_tile = [&](int kt) {
        const int k0 = kt * 64;
        const int bi = kt & 1;
        const uint32_t kfb = smem_u32(sm.Kf[bi]);
        const uint32_t vfb = smem_u32(sm.Vf[bi]);
        for (int s = tid; s < 64 * 16; s += 256) {
            int row = s >> 4, c16 = s & 15;
            CP_ASYNC16(kfb + (row * KSTR + c16 * 4) * 4,
                       Kfg + (size_t)(k0 + row) * HD + c16 * 8);
        }
        for (int s = tid; s < 128 * 8; s += 256) {
            int d = s >> 3, c8 = s & 7;
            CP_ASYNC16(vfb + (d * VSTR + c8 * 4) * 4,
                       Vfg + (size_t)d * T_ + k0 + c8 * 8);
        }
        CP_COMMIT();
    };

    issue_tile(0);

    for (int kt = 0; kt < ntiles; ++kt) {
        const int k0 = kt * 64;
        if (kt + 1 < ntiles) { issue_tile(kt + 1); CP_WAIT1(); }
        else                 { CP_WAIT0(); }
        __syncthreads();

        const uint32_t* KfB = sm.Kf[kt & 1];
        const uint32_t* VfB = sm.Vf[kt & 1];

        // ---- S = Q K^T (fp16 2-pass), warp tile 16x64 ----
        float cs[8][4];
#pragma unroll
        for (int nj = 0; nj < 8; ++nj)
#pragma unroll
            for (int r = 0; r < 4; ++r) cs[nj][r] = 0.f;

#pragma unroll
        for (int kf = 0; kf < 8; ++kf) {
            uint32_t qh[4], ql[4];
            int ab = (w * 16 + g) * KSTR + kf * 8 + tg;
            qh[0] = sm.Qh[ab];            qh[1] = sm.Qh[ab + 8 * KSTR];
            qh[2] = sm.Qh[ab + 4];        qh[3] = sm.Qh[ab + 8 * KSTR + 4];
            ql[0] = sm.Ql[ab];            ql[1] = sm.Ql[ab + 8 * KSTR];
            ql[2] = sm.Ql[ab + 4];        ql[3] = sm.Ql[ab + 8 * KSTR + 4];
#pragma unroll
            for (int nj = 0; nj < 8; ++nj) {
                int bb = (nj * 8 + g) * KSTR + kf * 8 + tg;
                uint32_t k2[2] = { KfB[bb], KfB[bb + 4] };
                mma_f16(cs[nj], qh, k2);
                mma_f16(cs[nj], ql, k2);
            }
        }

        // ---- causal mask ----
#pragma unroll
        for (int nj = 0; nj < 8; ++nj) {
            int c0 = k0 + nj * 8 + tg * 2, c1 = c0 + 1;
            cs[nj][0] = (c0 <= row0) ? cs[nj][0] : -1e30f;
            cs[nj][1] = (c1 <= row0) ? cs[nj][1] : -1e30f;
            cs[nj][2] = (c0 <= row1) ? cs[nj][2] : -1e30f;
            cs[nj][3] = (c1 <= row1) ? cs[nj][3] : -1e30f;
        }

        // ---- register softmax ----
        float mx0 = -1e30f, mx1 = -1e30f;
#pragma unroll
        for (int nj = 0; nj < 8; ++nj) {
            mx0 = fmaxf(mx0, fmaxf(cs[nj][0], cs[nj][1]));
            mx1 = fmaxf(mx1, fmaxf(cs[nj][2], cs[nj][3]));
        }
        mx0 = fmaxf(mx0, __shfl_xor_sync(0xffffffffu, mx0, 1));
        mx0 = fmaxf(mx0, __shfl_xor_sync(0xffffffffu, mx0, 2));
        mx1 = fmaxf(mx1, __shfl_xor_sync(0xffffffffu, mx1, 1));
        mx1 = fmaxf(mx1, __shfl_xor_sync(0xffffffffu, mx1, 2));

        float mn0 = fmaxf(m0, mx0), mn1 = fmaxf(m1, mx1);
        float al0 = __expf(m0 - mn0), al1 = __expf(m1 - mn1);
        float s0 = 0.f, s1 = 0.f;
#pragma unroll
        for (int nj = 0; nj < 8; ++nj) {
            cs[nj][0] = __expf(cs[nj][0] - mn0);
            cs[nj][1] = __expf(cs[nj][1] - mn0);
            cs[nj][2] = __expf(cs[nj][2] - mn1);
            cs[nj][3] = __expf(cs[nj][3] - mn1);
            s0 += cs[nj][0] + cs[nj][1];
            s1 += cs[nj][2] + cs[nj][3];
        }
        s0 += __shfl_xor_sync(0xffffffffu, s0, 1);
        s0 += __shfl_xor_sync(0xffffffffu, s0, 2);
        s1 += __shfl_xor_sync(0xffffffffu, s1, 1);
        s1 += __shfl_xor_sync(0xffffffffu, s1, 2);
        l0 = l0 * al0 + s0;
        l1 = l1 * al1 + s1;
        m0 = mn0; m1 = mn1;

#pragma unroll
        for (int t = 0; t < 16; ++t) {
            o[t][0] *= al0; o[t][1] *= al0;
            o[t][2] *= al1; o[t][3] *= al1;
        }

        // ---- O += P V (fp16 single-pass) ----
#pragma unroll
        for (int kf = 0; kf < 4; ++kf) {
            uint32_t pa[4];
            pa[0] = h2pack(cs[2 * kf][0],     cs[2 * kf][1]);
            pa[1] = h2pack(cs[2 * kf][2],     cs[2 * kf][3]);
            pa[2] = h2pack(cs[2 * kf + 1][0], cs[2 * kf + 1][1]);
            pa[3] = h2pack(cs[2 * kf + 1][2], cs[2 * kf + 1][3]);
#pragma unroll
            for (int nj = 0; nj < 16; ++nj) {
                int bb = (nj * 8 + g) * VSTR + kf * 8 + tg;
                uint32_t bv[2] = { VfB[bb], VfB[bb + 4] };
                mma_f16(o[nj], pa, bv);
            }
        }
        __syncthreads();
    }

    // ---- epilogue: normalize, split to fp16 hi/lo attn planes ----
    float i0 = 1.0f / l0, i1 = 1.0f / l1;
    int r0 = q0 + w * 16 + g, r1 = r0 + 8;
#pragma unroll
    for (int nj = 0; nj < 16; ++nj) {
        int col = nj * 8 + tg * 2;
        size_t o0 = (size_t)(b * T_ + r0) * HID + h * HD + col;
        size_t o1 = (size_t)(b * T_ + r1) * HID + h * HD + col;
        __half h0, lo0, h1, lo1;
        split1h(o[nj][0] * i0, h0, lo0);
        split1h(o[nj][1] * i0, h1, lo1);
        *(__half2*)&g_ah[o0] = __halves2half2(h0, h1);
        *(__half2*)&g_al[o0] = __halves2half2(lo0, lo1);
        split1h(o[nj][2] * i1, h0, lo0);
        split1h(o[nj][3] * i1, h1, lo1);
        *(__half2*)&g_ah[o1] = __halves2half2(h0, h1);
        *(__half2*)&g_al[o1] = __halves2half2(lo0, lo1);
    }
    (void)dummy;
}

// ---------------------------------------------------------------------------
// Launch
// ---------------------------------------------------------------------------
extern "C" void kernel_launch(void* const* d_in, const int* in_sizes, int n_in,
                              void* d_out, int out_size) {
    const float* x  = (const float*)d_in[0];
    const float* Wq = (const float*)d_in[2];
    const float* Wk = (const float*)d_in[3];
    const float* Wv = (const float*)d_in[4];
    const float* Wo = (const float*)d_in[5];
    float* out = (float*)d_out;

    void *p_qo, *p_ko, *p_vo;
    void *p_xh, *p_xl, *p_wqf, *p_wkf, *p_wvf, *p_wof;
    void *p_ah, *p_al;
    cudaGetSymbolAddress(&p_qo, g_qo);
    cudaGetSymbolAddress(&p_ko, g_ko);
    cudaGetSymbolAddress(&p_vo, g_vo);
    cudaGetSymbolAddress(&p_xh, g_xh);   cudaGetSymbolAddress(&p_xl, g_xl);
    cudaGetSymbolAddress(&p_wqf, g_wqf);
    cudaGetSymbolAddress(&p_wkf, g_wkf);
    cudaGetSymbolAddress(&p_wvf, g_wvf);
    cudaGetSymbolAddress(&p_wof, g_wof);
    cudaGetSymbolAddress(&p_ah, g_ah);   cudaGetSymbolAddress(&p_al, g_al);

    cudaFuncSetAttribute(flash_mma, cudaFuncAttributeMaxDynamicSharedMemorySize,
                         (int)sizeof(FlashSmem4));

    // Splits
    splith_kernel<<<8192, 256>>>(x, (__half*)p_xh, (__half*)p_xl, B_ * T_ * HID / 4);
    splitf_kernel<<<4096, 256>>>(Wq, (__half*)p_wqf, HID * HID / 4);
    splitf_kernel<<<1024, 256>>>(Wk, (__half*)p_wkf, NKV * HD * HID / 4);
    splitf_kernel<<<1024, 256>>>(Wv, (__half*)p_wvf, NKV * HD * HID / 4);
    splitf_kernel<<<4096, 256>>>(Wo, (__half*)p_wof, HID * HID / 4);

    // QKV projections (fp16 2-pass)
    gemm_f16<<<dim3(16, 32), 256>>>((const __half*)p_xh, (const __half*)p_xl,
                                    (const __half*)p_wqf, (float*)p_qo, B_ * T_, NH * HD, HID);
    gemm_f16<<<dim3(4, 32), 256>>>((const __half*)p_xh, (const __half*)p_xl,
                                   (const __half*)p_wkf, (float*)p_ko, B_ * T_, NKV * HD, HID);
    gemm_f16<<<dim3(4, 32), 256>>>((const __half*)p_xh, (const __half*)p_xl,
                                   (const __half*)p_wvf, (float*)p_vo, B_ * T_, NKV * HD, HID);

    // RoPE + V transpose
    rope_q_kernel<<<(B_ * T_ * NH * 64) / 256, 256>>>();
    rope_k_kernel<<<(B_ * T_ * NKV * 64) / 256, 256>>>();
    vt_kernel<<<dim3(T_ / 32, HD / 32, B_ * NKV), dim3(32, 8)>>>();

    // Flash attention
    flash_mma<<<dim3(T_ / 128, NH, B_), 256, sizeof(FlashSmem4)>>>(nullptr);

    // Output projection (fp16 2-pass)
    gemm_f16<<<dim3(16, 32), 256>>>((const __half*)p_ah, (const __half*)p_al,
                                    (const __half*)p_wof, out, B_ * T_, HID, HID);
}

// round 14
// speedup vs baseline: 3.9265x; 1.1619x over previous
#include <cuda_runtime.h>
#include <cuda_bf16.h>
#include <cuda_fp16.h>
#include <math.h>
#include <cstdint>

#define B_   2
#define T_   2048
#define HID  2048
#define NH   16
#define NKV  4
#define HD   128

// ---------------------------------------------------------------------------
// Global scratch
// ---------------------------------------------------------------------------
__device__ __align__(256) float g_qo[(size_t)B_ * T_ * NH * HD];
__device__ __align__(256) float g_ko[(size_t)B_ * T_ * NKV * HD];
__device__ __align__(256) float g_vo[(size_t)B_ * T_ * NKV * HD];

__device__ __align__(256) __half g_xh[(size_t)B_ * T_ * HID];
__device__ __align__(256) __half g_xl[(size_t)B_ * T_ * HID];
__device__ __align__(256) __half g_wqf[(size_t)HID * HID];
__device__ __align__(256) __half g_wkf[(size_t)NKV * HD * HID];
__device__ __align__(256) __half g_wvf[(size_t)NKV * HD * HID];
__device__ __align__(256) __half g_wof[(size_t)HID * HID];

__device__ __align__(256) __half g_qpf[(size_t)B_ * NH * T_ * HD];   // Q single
__device__ __align__(256) __half g_kpf[(size_t)B_ * NKV * T_ * HD];  // K single
__device__ __align__(256) __half g_vtf[(size_t)B_ * NKV * HD * T_];  // V^T single
__device__ __align__(256) __half g_af[(size_t)B_ * T_ * HID];        // attn single

// ---------------------------------------------------------------------------
// Helpers
// ---------------------------------------------------------------------------
__device__ __forceinline__ uint32_t smem_u32(const void* p) {
    uint32_t a;
    asm("{ .reg .u64 t; cvta.to.shared.u64 t, %1; cvt.u32.u64 %0, t; }"
        : "=r"(a) : "l"(p));
    return a;
}

#define CP_ASYNC16(dst, src) \
    asm volatile("cp.async.cg.shared.global [%0], [%1], 16;" :: "r"(dst), "l"(src))
#define CP_COMMIT() asm volatile("cp.async.commit_group;" ::: "memory")
#define CP_WAIT0()  asm volatile("cp.async.wait_group 0;" ::: "memory")
#define CP_WAIT1()  asm volatile("cp.async.wait_group 1;" ::: "memory")

__device__ __forceinline__ void mma_f16(float* c, const uint32_t* a, const uint32_t* b) {
    asm volatile(
        "mma.sync.aligned.m16n8k16.row.col.f32.f16.f16.f32 "
        "{%0,%1,%2,%3}, {%4,%5,%6,%7}, {%8,%9}, {%0,%1,%2,%3};"
        : "+f"(c[0]), "+f"(c[1]), "+f"(c[2]), "+f"(c[3])
        : "r"(a[0]), "r"(a[1]), "r"(a[2]), "r"(a[3]), "r"(b[0]), "r"(b[1]));
}

__device__ __forceinline__ void split1h(float v, __half& h, __half& l) {
    h = __float2half_rn(v);
    l = __float2half_rn(v - __half2float(h));
}
__device__ __forceinline__ uint32_t h2pack(float a, float b) {
    __half2 h = __floats2half2_rn(a, b);
    return *(uint32_t*)&h;
}

// ---------------------------------------------------------------------------
// Split passes
// ---------------------------------------------------------------------------
__global__ void splith_kernel(const float* __restrict__ in, __half* __restrict__ oh,
                              __half* __restrict__ ol, int n4) {
    int i = blockIdx.x * 256 + threadIdx.x;
    if (i >= n4) return;
    float4 v = ((const float4*)in)[i];
    __half h0, l0, h1, l1, h2, l2, h3, l3;
    split1h(v.x, h0, l0); split1h(v.y, h1, l1);
    split1h(v.z, h2, l2); split1h(v.w, h3, l3);
    ((__half2*)oh)[2 * i]     = __halves2half2(h0, h1);
    ((__half2*)oh)[2 * i + 1] = __halves2half2(h2, h3);
    ((__half2*)ol)[2 * i]     = __halves2half2(l0, l1);
    ((__half2*)ol)[2 * i + 1] = __halves2half2(l2, l3);
}

__global__ void splitf_kernel(const float* __restrict__ in, __half* __restrict__ o, int n4) {
    int i = blockIdx.x * 256 + threadIdx.x;
    if (i >= n4) return;
    float4 v = ((const float4*)in)[i];
    ((__half2*)o)[2 * i]     = __floats2half2_rn(v.x, v.y);
    ((__half2*)o)[2 * i + 1] = __floats2half2_rn(v.z, v.w);
}

// ---------------------------------------------------------------------------
// GEMM NT fp16 2-pass: C = (Ah+Al) @ B^T  (A split fp16x2, B single fp16)
// ---------------------------------------------------------------------------
#define GSTR 12
#define GPLANE (128 * GSTR)

__global__ __launch_bounds__(256) void gemm_f16(const __half* __restrict__ Ah,
                                                const __half* __restrict__ Al,
                                                const __half* __restrict__ Bf,
                                                float* __restrict__ C,
                                                int M, int N_, int K) {
    __shared__ __align__(16) uint32_t sm[2][3][GPLANE];
    const int tid = threadIdx.x;
    const int lane = tid & 31, wid = tid >> 5;
    const int g = lane >> 2, tg = lane & 3;
    const int m0 = blockIdx.y * 128, n0 = blockIdx.x * 128;
    const int mw = (wid >> 2) * 64, nw = (wid & 3) * 32;

    float acc[4][4][4];
#pragma unroll
    for (int mi = 0; mi < 4; ++mi)
#pragma unroll
        for (int nj = 0; nj < 4; ++nj)
#pragma unroll
            for (int r = 0; r < 4; ++r) acc[mi][nj][r] = 0.f;

    const int rr = tid >> 1;
    const int hc = (tid & 1) * 8;
    const __half* src[3] = {
        Ah + (size_t)(m0 + rr) * K + hc, Al + (size_t)(m0 + rr) * K + hc,
        Bf + (size_t)(n0 + rr) * K + hc };
    uint32_t dst0[3];
#pragma unroll
    for (int p = 0; p < 3; ++p)
        dst0[p] = smem_u32(&sm[0][p][rr * GSTR + (tid & 1) * 4]);
    const uint32_t bufB = 3 * GPLANE * 4;

#pragma unroll
    for (int p = 0; p < 3; ++p) CP_ASYNC16(dst0[p], src[p]);
    CP_COMMIT();

    const int nkt = K >> 4;
    for (int kt = 0; kt < nkt; ++kt) {
        CP_WAIT0();
        __syncthreads();
        if (kt + 1 < nkt) {
            const int k0 = (kt + 1) << 4;
            const uint32_t bo = ((kt + 1) & 1) * bufB;
#pragma unroll
            for (int p = 0; p < 3; ++p) CP_ASYNC16(dst0[p] + bo, src[p] + k0);
            CP_COMMIT();
        }
        const uint32_t (*cur)[GPLANE] = sm[kt & 1];

        uint32_t ah[4][4], al[4][4], bh[4][2];
#pragma unroll
        for (int mi = 0; mi < 4; ++mi) {
            int base = (mw + mi * 16 + g) * GSTR + tg;
            ah[mi][0] = cur[0][base];      ah[mi][1] = cur[0][base + 8 * GSTR];
            ah[mi][2] = cur[0][base + 4];  ah[mi][3] = cur[0][base + 8 * GSTR + 4];
            al[mi][0] = cur[1][base];      al[mi][1] = cur[1][base + 8 * GSTR];
            al[mi][2] = cur[1][base + 4];  al[mi][3] = cur[1][base + 8 * GSTR + 4];
        }
#pragma unroll
        for (int nj = 0; nj < 4; ++nj) {
            int base = (nw + nj * 8 + g) * GSTR + tg;
            bh[nj][0] = cur[2][base]; bh[nj][1] = cur[2][base + 4];
        }
#pragma unroll
        for (int mi = 0; mi < 4; ++mi)
#pragma unroll
            for (int nj = 0; nj < 4; ++nj) {
                mma_f16(acc[mi][nj], ah[mi], bh[nj]);
                mma_f16(acc[mi][nj], al[mi], bh[nj]);
            }
    }

#pragma unroll
    for (int mi = 0; mi < 4; ++mi) {
#pragma unroll
        for (int nj = 0; nj < 4; ++nj) {
            int row = m0 + mw + mi * 16 + g;
            int col = n0 + nw + nj * 8 + tg * 2;
            *(float2*)(C + (size_t)row * N_ + col) =
                make_float2(acc[mi][nj][0], acc[mi][nj][1]);
            *(float2*)(C + (size_t)(row + 8) * N_ + col) =
                make_float2(acc[mi][nj][2], acc[mi][nj][3]);
        }
    }
}

// ---------------------------------------------------------------------------
// GEMM NT fp16 single-pass: C = A @ B^T  (A single fp16, B single fp16)
// ---------------------------------------------------------------------------
__global__ __launch_bounds__(256) void gemm_f16s(const __half* __restrict__ Af,
                                                 const __half* __restrict__ Bf,
                                                 float* __restrict__ C,
                                                 int M, int N_, int K) {
    __shared__ __align__(16) uint32_t sm[2][2][GPLANE];
    const int tid = threadIdx.x;
    const int lane = tid & 31, wid = tid >> 5;
    const int g = lane >> 2, tg = lane & 3;
    const int m0 = blockIdx.y * 128, n0 = blockIdx.x * 128;
    const int mw = (wid >> 2) * 64, nw = (wid & 3) * 32;

    float acc[4][4][4];
#pragma unroll
    for (int mi = 0; mi < 4; ++mi)
#pragma unroll
        for (int nj = 0; nj < 4; ++nj)
#pragma unroll
            for (int r = 0; r < 4; ++r) acc[mi][nj][r] = 0.f;

    const int rr = tid >> 1;
    const int hc = (tid & 1) * 8;
    const __half* src[2] = {
        Af + (size_t)(m0 + rr) * K + hc, Bf + (size_t)(n0 + rr) * K + hc };
    uint32_t dst0[2];
#pragma unroll
    for (int p = 0; p < 2; ++p)
        dst0[p] = smem_u32(&sm[0][p][rr * GSTR + (tid & 1) * 4]);
    const uint32_t bufB = 2 * GPLANE * 4;

#pragma unroll
    for (int p = 0; p < 2; ++p) CP_ASYNC16(dst0[p], src[p]);
    CP_COMMIT();

    const int nkt = K >> 4;
    for (int kt = 0; kt < nkt; ++kt) {
        CP_WAIT0();
        __syncthreads();
        if (kt + 1 < nkt) {
            const int k0 = (kt + 1) << 4;
            const uint32_t bo = ((kt + 1) & 1) * bufB;
#pragma unroll
            for (int p = 0; p < 2; ++p) CP_ASYNC16(dst0[p] + bo, src[p] + k0);
            CP_COMMIT();
        }
        const uint32_t (*cur)[GPLANE] = sm[kt & 1];

        uint32_t ah[4][4], bh[4][2];
#pragma unroll
        for (int mi = 0; mi < 4; ++mi) {
            int base = (mw + mi * 16 + g) * GSTR + tg;
            ah[mi][0] = cur[0][base];      ah[mi][1] = cur[0][base + 8 * GSTR];
            ah[mi][2] = cur[0][base + 4];  ah[mi][3] = cur[0][base + 8 * GSTR + 4];
        }
#pragma unroll
        for (int nj = 0; nj < 4; ++nj) {
            int base = (nw + nj * 8 + g) * GSTR + tg;
            bh[nj][0] = cur[1][base]; bh[nj][1] = cur[1][base + 4];
        }
#pragma unroll
        for (int mi = 0; mi < 4; ++mi)
#pragma unroll
            for (int nj = 0; nj < 4; ++nj)
                mma_f16(acc[mi][nj], ah[mi], bh[nj]);
    }

#pragma unroll
    for (int mi = 0; mi < 4; ++mi) {
#pragma unroll
        for (int nj = 0; nj < 4; ++nj) {
            int row = m0 + mw + mi * 16 + g;
            int col = n0 + nw + nj * 8 + tg * 2;
            *(float2*)(C + (size_t)row * N_ + col) =
                make_float2(acc[mi][nj][0], acc[mi][nj][1]);
            *(float2*)(C + (size_t)(row + 8) * N_ + col) =
                make_float2(acc[mi][nj][2], acc[mi][nj][3]);
        }
    }
}

// ---------------------------------------------------------------------------
// RoPE: Q -> single fp16 plane (scale folded), K -> single fp16 plane
// ---------------------------------------------------------------------------
__global__ void rope_q_kernel() {
    int idx = blockIdx.x * 256 + threadIdx.x;
    int j = idx & 63;
    int h = (idx >> 6) & (NH - 1);
    int t = (idx >> 10) & (T_ - 1);
    int b = idx >> 21;
    float inv = powf(10000.0f, -(float)j / 64.0f);
    float s, c;
    sincosf((float)t * inv, &s, &c);
    const float scale = 0.08838834764831845f;
    const float* src = g_qo + (size_t)(b * T_ + t) * (NH * HD) + h * HD;
    float x1 = src[j], x2 = src[j + 64];
    size_t o = ((size_t)(b * NH + h) * T_ + t) * HD;
    g_qpf[o + j]      = __float2half_rn((x1 * c - x2 * s) * scale);
    g_qpf[o + j + 64] = __float2half_rn((x2 * c + x1 * s) * scale);
}

__global__ void rope_k_kernel() {
    int idx = blockIdx.x * 256 + threadIdx.x;
    int j  = idx & 63;
    int kh = (idx >> 6) & (NKV - 1);
    int t  = (idx >> 8) & (T_ - 1);
    int b  = idx >> 19;
    float inv = powf(10000.0f, -(float)j / 64.0f);
    float s, c;
    sincosf((float)t * inv, &s, &c);
    const float* src = g_ko + (size_t)(b * T_ + t) * (NKV * HD) + kh * HD;
    float x1 = src[j], x2 = src[j + 64];
    size_t o = ((size_t)(b * NKV + kh) * T_ + t) * HD;
    g_kpf[o + j]      = __float2half_rn(x1 * c - x2 * s);
    g_kpf[o + j + 64] = __float2half_rn(x2 * c + x1 * s);
}

// ---------------------------------------------------------------------------
// V transpose: fp32 [b*T+t][kh*128+d] -> single fp16 [(b,kh)*128+d][T]
// ---------------------------------------------------------------------------
__global__ void vt_kernel() {
    __shared__ float tl[32][33];
    int tx = threadIdx.x, ty = threadIdx.y;
    int t0 = blockIdx.x * 32, d0 = blockIdx.y * 32, bk = blockIdx.z;
    int b = bk >> 2, kh = bk & 3;
#pragma unroll
    for (int i = 0; i < 4; ++i)
        tl[ty + 8 * i][tx] =
            g_vo[(size_t)(b * T_ + t0 + ty + 8 * i) * (NKV * HD) + kh * HD + d0 + tx];
    __syncthreads();
#pragma unroll
    for (int i = 0; i < 4; ++i) {
        int dd = ty + 8 * i;
        g_vtf[((size_t)bk * HD + d0 + dd) * T_ + t0 + tx] = __float2half_rn(tl[tx][dd]);
    }
}

// ---------------------------------------------------------------------------
// Flash attention: S fp16 1-pass (Q single x K single), PV fp16 1-pass,
// register softmax, double-buffered cp.async K/V. 8 warps x 16 q-rows, BN=64.
// ---------------------------------------------------------------------------
#define KSTR 68   // u32 per Q/K row (272 B)
#define VSTR 36   // u32 per V row (144 B)

struct FlashSmem5 {
    uint32_t Qf[128 * KSTR];
    uint32_t Kf[2][64 * KSTR];
    uint32_t Vf[2][128 * VSTR];
};
static_assert(sizeof(FlashSmem5) <= 227 * 1024, "smem too big");

__global__ __launch_bounds__(256, 1) void flash_mma(float* dummy) {
    extern __shared__ unsigned char smraw[];
    FlashSmem5& sm = *reinterpret_cast<FlashSmem5*>(smraw);
    const int tid = threadIdx.x;
    const int lane = tid & 31, w = tid >> 5;
    const int g = lane >> 2, tg = lane & 3;
    const int b = blockIdx.z, h = blockIdx.y;
    const int q0 = blockIdx.x * 128;
    const int kh = h >> 2;

    const __half* Qfg = g_qpf + ((size_t)(b * NH + h) * T_ + q0) * HD;
    const __half* Kfg = g_kpf + (size_t)(b * NKV + kh) * T_ * HD;
    const __half* Vfg = g_vtf + (size_t)(b * NKV + kh) * HD * T_;

    // Q tile load
    for (int s = tid; s < 128 * 16; s += 256) {
        int row = s >> 4, c16 = s & 15;
        *(uint4*)&sm.Qf[row * KSTR + c16 * 4] = *(const uint4*)(Qfg + (size_t)row * HD + c16 * 8);
    }

    float o[16][4];
#pragma unroll
    for (int t = 0; t < 16; ++t)
#pragma unroll
        for (int r = 0; r < 4; ++r) o[t][r] = 0.f;
    float m0 = -1e30f, m1 = -1e30f, l0 = 0.f, l1 = 0.f;

    const int row0 = q0 + w * 16 + g;
    const int row1 = row0 + 8;
    const int ntiles = (q0 >> 6) + 2;

    auto issue_tile = [&](int kt) {
        const int k0 = kt * 64;
        const int bi = kt & 1;
        const uint32_t kfb = smem_u32(sm.Kf[bi]);
        const uint32_t vfb = smem_u32(sm.Vf[bi]);
        for (int s = tid; s < 64 * 16; s += 256) {
            int row = s >> 4, c16 = s & 15;
            CP_ASYNC16(kfb + (row * KSTR + c16 * 4) * 4,
                       Kfg + (size_t)(k0 + row) * HD + c16 * 8);
        }
        for (int s = tid; s < 128 * 8; s += 256) {
            int d = s >> 3, c8 = s & 7;
            CP_ASYNC16(vfb + (d * VSTR + c8 * 4) * 4,
                       Vfg + (size_t)d * T_ + k0 + c8 * 8);
        }
        CP_COMMIT();
    };

    issue_tile(0);

    for (int kt = 0; kt < ntiles; ++kt) {
        const int k0 = kt * 64;
        if (kt + 1 < ntiles) { issue_tile(kt + 1); CP_WAIT1(); }
        else                 { CP_WAIT0(); }
        __syncthreads();

        const uint32_t* KfB = sm.Kf[kt & 1];
        const uint32_t* VfB = sm.Vf[kt & 1];

        // ---- S = Q K^T (fp16 single-pass), warp tile 16x64 ----
        float cs[8][4];
#pragma unroll
        for (int nj = 0; nj < 8; ++nj)
#pragma unroll
            for (int r = 0; r < 4; ++r) cs[nj][r] = 0.f;

#pragma unroll
        for (int kf = 0; kf < 8; ++kf) {
            uint32_t qf[4];
            int ab = (w * 16 + g) * KSTR + kf * 8 + tg;
            qf[0] = sm.Qf[ab];            qf[1] = sm.Qf[ab + 8 * KSTR];
            qf[2] = sm.Qf[ab + 4];        qf[3] = sm.Qf[ab + 8 * KSTR + 4];
#pragma unroll
            for (int nj = 0; nj < 8; ++nj) {
                int bb = (nj * 8 + g) * KSTR + kf * 8 + tg;
                uint32_t k2[2] = { KfB[bb], KfB[bb + 4] };
                mma_f16(cs[nj], qf, k2);
            }
        }

        // ---- causal mask ----
#pragma unroll
        for (int nj = 0; nj < 8; ++nj) {
            int c0 = k0 + nj * 8 + tg * 2, c1 = c0 + 1;
            cs[nj][0] = (c0 <= row0) ? cs[nj][0] : -1e30f;
            cs[nj][1] = (c1 <= row0) ? cs[nj][1] : -1e30f;
            cs[nj][2] = (c0 <= row1) ? cs[nj][2] : -1e30f;
            cs[nj][3] = (c1 <= row1) ? cs[nj][3] : -1e30f;
        }

        // ---- register softmax ----
        float mx0 = -1e30f, mx1 = -1e30f;
#pragma unroll
        for (int nj = 0; nj < 8; ++nj) {
            mx0 = fmaxf(mx0, fmaxf(cs[nj][0], cs[nj][1]));
            mx1 = fmaxf(mx1, fmaxf(cs[nj][2], cs[nj][3]));
        }
        mx0 = fmaxf(mx0, __shfl_xor_sync(0xffffffffu, mx0, 1));
        mx0 = fmaxf(mx0, __shfl_xor_sync(0xffffffffu, mx0, 2));
        mx1 = fmaxf(mx1, __shfl_xor_sync(0xffffffffu, mx1, 1));
        mx1 = fmaxf(mx1, __shfl_xor_sync(0xffffffffu, mx1, 2));

        float mn0 = fmaxf(m0, mx0), mn1 = fmaxf(m1, mx1);
        float al0 = __expf(m0 - mn0), al1 = __expf(m1 - mn1);
        float s0 = 0.f, s1 = 0.f;
#pragma unroll
        for (int nj = 0; nj < 8; ++nj) {
            cs[nj][0] = __expf(cs[nj][0] - mn0);
            cs[nj][1] = __expf(cs[nj][1] - mn0);
            cs[nj][2] = __expf(cs[nj][2] - mn1);
            cs[nj][3] = __expf(cs[nj][3] - mn1);
            s0 += cs[nj][0] + cs[nj][1];
            s1 += cs[nj][2] + cs[nj][3];
        }
        s0 += __shfl_xor_sync(0xffffffffu, s0, 1);
        s0 += __shfl_xor_sync(0xffffffffu, s0, 2);
        s1 += __shfl_xor_sync(0xffffffffu, s1, 1);
        s1 += __shfl_xor_sync(0xffffffffu, s1, 2);
        l0 = l0 * al0 + s0;
        l1 = l1 * al1 + s1;
        m0 = mn0; m1 = mn1;

#pragma unroll
        for (int t = 0; t < 16; ++t) {
            o[t][0] *= al0; o[t][1] *= al0;
            o[t][2] *= al1; o[t][3] *= al1;
        }

        // ---- O += P V (fp16 single-pass) ----
#pragma unroll
        for (int kf = 0; kf < 4; ++kf) {
            uint32_t pa[4];
            pa[0] = h2pack(cs[2 * kf][0],     cs[2 * kf][1]);
            pa[1] = h2pack(cs[2 * kf][2],     cs[2 * kf][3]);
            pa[2] = h2pack(cs[2 * kf + 1][0], cs[2 * kf + 1][1]);
            pa[3] = h2pack(cs[2 * kf + 1][2], cs[2 * kf + 1][3]);
#pragma unroll
            for (int nj = 0; nj < 16; ++nj) {
                int bb = (nj * 8 + g) * VSTR + kf * 8 + tg;
                uint32_t bv[2] = { VfB[bb], VfB[bb + 4] };
                mma_f16(o[nj], pa, bv);
            }
        }
        __syncthreads();
    }

    // ---- epilogue: normalize, write single fp16 attn plane ----
    float i0 = 1.0f / l0, i1 = 1.0f / l1;
    int r0 = q0 + w * 16 + g, r1 = r0 + 8;
#pragma unroll
    for (int nj = 0; nj < 16; ++nj) {
        int col = nj * 8 + tg * 2;
        size_t o0 = (size_t)(b * T_ + r0) * HID + h * HD + col;
        size_t o1 = (size_t)(b * T_ + r1) * HID + h * HD + col;
        *(__half2*)&g_af[o0] = __floats2half2_rn(o[nj][0] * i0, o[nj][1] * i0);
        *(__half2*)&g_af[o1] = __floats2half2_rn(o[nj][2] * i1, o[nj][3] * i1);
    }
    (void)dummy;
}

// ---------------------------------------------------------------------------
// Launch
// ---------------------------------------------------------------------------
extern "C" void kernel_launch(void* const* d_in, const int* in_sizes, int n_in,
                              void* d_out, int out_size) {
    const float* x  = (const float*)d_in[0];
    const float* Wq = (const float*)d_in[2];
    const float* Wk = (const float*)d_in[3];
    const float* Wv = (const float*)d_in[4];
    const float* Wo = (const float*)d_in[5];
    float* out = (float*)d_out;

    void *p_qo, *p_ko, *p_vo;
    void *p_xh, *p_xl, *p_wqf, *p_wkf, *p_wvf, *p_wof;
    void *p_af;
    cudaGetSymbolAddress(&p_qo, g_qo);
    cudaGetSymbolAddress(&p_ko, g_ko);
    cudaGetSymbolAddress(&p_vo, g_vo);
    cudaGetSymbolAddress(&p_xh, g_xh);   cudaGetSymbolAddress(&p_xl, g_xl);
    cudaGetSymbolAddress(&p_wqf, g_wqf);
    cudaGetSymbolAddress(&p_wkf, g_wkf);
    cudaGetSymbolAddress(&p_wvf, g_wvf);
    cudaGetSymbolAddress(&p_wof, g_wof);
    cudaGetSymbolAddress(&p_af, g_af);

    cudaFuncSetAttribute(flash_mma, cudaFuncAttributeMaxDynamicSharedMemorySize,
                         (int)sizeof(FlashSmem5));

    // Splits
    splith_kernel<<<8192, 256>>>(x, (__half*)p_xh, (__half*)p_xl, B_ * T_ * HID / 4);
    splitf_kernel<<<4096, 256>>>(Wq, (__half*)p_wqf, HID * HID / 4);
    splitf_kernel<<<1024, 256>>>(Wk, (__half*)p_wkf, NKV * HD * HID / 4);
    splitf_kernel<<<1024, 256>>>(Wv, (__half*)p_wvf, NKV * HD * HID / 4);
    splitf_kernel<<<4096, 256>>>(Wo, (__half*)p_wof, HID * HID / 4);

    // QKV projections (fp16 2-pass)
    gemm_f16<<<dim3(16, 32), 256>>>((const __half*)p_xh, (const __half*)p_xl,
                                    (const __half*)p_wqf, (float*)p_qo, B_ * T_, NH * HD, HID);
    gemm_f16<<<dim3(4, 32), 256>>>((const __half*)p_xh, (const __half*)p_xl,
                                   (const __half*)p_wkf, (float*)p_ko, B_ * T_, NKV * HD, HID);
    gemm_f16<<<dim3(4, 32), 256>>>((const __half*)p_xh, (const __half*)p_xl,
                                   (const __half*)p_wvf, (float*)p_vo, B_ * T_, NKV * HD, HID);

    // RoPE + V transpose
    rope_q_kernel<<<(B_ * T_ * NH * 64) / 256, 256>>>();
    rope_k_kernel<<<(B_ * T_ * NKV * 64) / 256, 256>>>();
    vt_kernel<<<dim3(T_ / 32, HD / 32, B_ * NKV), dim3(32, 8)>>>();

    // Flash attention (writes single fp16 attn)
    flash_mma<<<dim3(T_ / 128, NH, B_), 256, sizeof(FlashSmem5)>>>(nullptr);

    // Output projection (fp16 single-pass)
    gemm_f16s<<<dim3(16, 32), 256>>>((const __half*)p_af, (const __half*)p_wof,
                                     out, B_ * T_, HID, HID);
}

// round 16
// speedup vs baseline: 4.7468x; 1.2089x over previous
#include <cuda_runtime.h>
#include <cuda_bf16.h>
#include <cuda_fp16.h>
#include <math.h>
#include <cstdint>

#define B_   2
#define T_   2048
#define HID  2048
#define NH   16
#define NKV  4
#define HD   128

// ---------------------------------------------------------------------------
// Global scratch
// ---------------------------------------------------------------------------
__device__ __align__(256) float g_qo[(size_t)B_ * T_ * NH * HD];
__device__ __align__(256) float g_ko[(size_t)B_ * T_ * NKV * HD];
__device__ __align__(256) float g_vo[(size_t)B_ * T_ * NKV * HD];

__device__ __align__(256) __half g_xf[(size_t)B_ * T_ * HID];        // x single
__device__ __align__(256) __half g_wqf[(size_t)HID * HID];
__device__ __align__(256) __half g_wkf[(size_t)NKV * HD * HID];
__device__ __align__(256) __half g_wvf[(size_t)NKV * HD * HID];
__device__ __align__(256) __half g_wof[(size_t)HID * HID];

__device__ __align__(256) __half g_qpf[(size_t)B_ * NH * T_ * HD];   // Q single
__device__ __align__(256) __half g_kpf[(size_t)B_ * NKV * T_ * HD];  // K single
__device__ __align__(256) __half g_vtf[(size_t)B_ * NKV * HD * T_];  // V^T single
__device__ __align__(256) __half g_af[(size_t)B_ * T_ * HID];        // attn single

// ---------------------------------------------------------------------------
// Helpers
// ---------------------------------------------------------------------------
__device__ __forceinline__ uint32_t smem_u32(const void* p) {
    uint32_t a;
    asm("{ .reg .u64 t; cvta.to.shared.u64 t, %1; cvt.u32.u64 %0, t; }"
        : "=r"(a) : "l"(p));
    return a;
}

#define CP_ASYNC16(dst, src) \
    asm volatile("cp.async.cg.shared.global [%0], [%1], 16;" :: "r"(dst), "l"(src))
#define CP_COMMIT() asm volatile("cp.async.commit_group;" ::: "memory")
#define CP_WAIT0()  asm volatile("cp.async.wait_group 0;" ::: "memory")
#define CP_WAIT1()  asm volatile("cp.async.wait_group 1;" ::: "memory")

__device__ __forceinline__ void mma_f16(float* c, const uint32_t* a, const uint32_t* b) {
    asm volatile(
        "mma.sync.aligned.m16n8k16.row.col.f32.f16.f16.f32 "
        "{%0,%1,%2,%3}, {%4,%5,%6,%7}, {%8,%9}, {%0,%1,%2,%3};"
        : "+f"(c[0]), "+f"(c[1]), "+f"(c[2]), "+f"(c[3])
        : "r"(a[0]), "r"(a[1]), "r"(a[2]), "r"(a[3]), "r"(b[0]), "r"(b[1]));
}

__device__ __forceinline__ uint32_t h2pack(float a, float b) {
    __half2 h = __floats2half2_rn(a, b);
    return *(uint32_t*)&h;
}

// ---------------------------------------------------------------------------
// Split pass: fp32 -> single fp16
// ---------------------------------------------------------------------------
__global__ void splitf_kernel(const float* __restrict__ in, __half* __restrict__ o, int n4) {
    int i = blockIdx.x * 256 + threadIdx.x;
    if (i >= n4) return;
    float4 v = ((const float4*)in)[i];
    ((__half2*)o)[2 * i]     = __floats2half2_rn(v.x, v.y);
    ((__half2*)o)[2 * i + 1] = __floats2half2_rn(v.z, v.w);
}

// ---------------------------------------------------------------------------
// GEMM NT fp16 single-pass: C = A @ B^T  (A single fp16, B single fp16)
// 128x128 tile, BK=16, 8 warps (2m x 4n), cp.async double-buffered.
// ---------------------------------------------------------------------------
#define GSTR 12
#define GPLANE (128 * GSTR)

__global__ __launch_bounds__(256) void gemm_f16s(const __half* __restrict__ Af,
                                                 const __half* __restrict__ Bf,
                                                 float* __restrict__ C,
                                                 int M, int N_, int K) {
    __shared__ __align__(16) uint32_t sm[2][2][GPLANE];
    const int tid = threadIdx.x;
    const int lane = tid & 31, wid = tid >> 5;
    const int g = lane >> 2, tg = lane & 3;
    const int m0 = blockIdx.y * 128, n0 = blockIdx.x * 128;
    const int mw = (wid >> 2) * 64, nw = (wid & 3) * 32;

    float acc[4][4][4];
#pragma unroll
    for (int mi = 0; mi < 4; ++mi)
#pragma unroll
        for (int nj = 0; nj < 4; ++nj)
#pragma unroll
            for (int r = 0; r < 4; ++r) acc[mi][nj][r] = 0.f;

    const int rr = tid >> 1;
    const int hc = (tid & 1) * 8;
    const __half* src[2] = {
        Af + (size_t)(m0 + rr) * K + hc, Bf + (size_t)(n0 + rr) * K + hc };
    uint32_t dst0[2];
#pragma unroll
    for (int p = 0; p < 2; ++p)
        dst0[p] = smem_u32(&sm[0][p][rr * GSTR + (tid & 1) * 4]);
    const uint32_t bufB = 2 * GPLANE * 4;

#pragma unroll
    for (int p = 0; p < 2; ++p) CP_ASYNC16(dst0[p], src[p]);
    CP_COMMIT();

    const int nkt = K >> 4;
    for (int kt = 0; kt < nkt; ++kt) {
        CP_WAIT0();
        __syncthreads();
        if (kt + 1 < nkt) {
            const int k0 = (kt + 1) << 4;
            const uint32_t bo = ((kt + 1) & 1) * bufB;
#pragma unroll
            for (int p = 0; p < 2; ++p) CP_ASYNC16(dst0[p] + bo, src[p] + k0);
            CP_COMMIT();
        }
        const uint32_t (*cur)[GPLANE] = sm[kt & 1];

        uint32_t ah[4][4], bh[4][2];
#pragma unroll
        for (int mi = 0; mi < 4; ++mi) {
            int base = (mw + mi * 16 + g) * GSTR + tg;
            ah[mi][0] = cur[0][base];      ah[mi][1] = cur[0][base + 8 * GSTR];
            ah[mi][2] = cur[0][base + 4];  ah[mi][3] = cur[0][base + 8 * GSTR + 4];
        }
#pragma unroll
        for (int nj = 0; nj < 4; ++nj) {
            int base = (nw + nj * 8 + g) * GSTR + tg;
            bh[nj][0] = cur[1][base]; bh[nj][1] = cur[1][base + 4];
        }
#pragma unroll
        for (int mi = 0; mi < 4; ++mi)
#pragma unroll
            for (int nj = 0; nj < 4; ++nj)
                mma_f16(acc[mi][nj], ah[mi], bh[nj]);
    }

#pragma unroll
    for (int mi = 0; mi < 4; ++mi) {
#pragma unroll
        for (int nj = 0; nj < 4; ++nj) {
            int row = m0 + mw + mi * 16 + g;
            int col = n0 + nw + nj * 8 + tg * 2;
            *(float2*)(C + (size_t)row * N_ + col) =
                make_float2(acc[mi][nj][0], acc[mi][nj][1]);
            *(float2*)(C + (size_t)(row + 8) * N_ + col) =
                make_float2(acc[mi][nj][2], acc[mi][nj][3]);
        }
    }
}

// ---------------------------------------------------------------------------
// RoPE: Q -> single fp16 plane (scale folded), K -> single fp16 plane
// ---------------------------------------------------------------------------
__global__ void rope_q_kernel() {
    int idx = blockIdx.x * 256 + threadIdx.x;
    int j = idx & 63;
    int h = (idx >> 6) & (NH - 1);
    int t = (idx >> 10) & (T_ - 1);
    int b = idx >> 21;
    float inv = powf(10000.0f, -(float)j / 64.0f);
    float s, c;
    sincosf((float)t * inv, &s, &c);
    const float scale = 0.08838834764831845f;
    const float* src = g_qo + (size_t)(b * T_ + t) * (NH * HD) + h * HD;
    float x1 = src[j], x2 = src[j + 64];
    size_t o = ((size_t)(b * NH + h) * T_ + t) * HD;
    g_qpf[o + j]      = __float2half_rn((x1 * c - x2 * s) * scale);
    g_qpf[o + j + 64] = __float2half_rn((x2 * c + x1 * s) * scale);
}

__global__ void rope_k_kernel() {
    int idx = blockIdx.x * 256 + threadIdx.x;
    int j  = idx & 63;
    int kh = (idx >> 6) & (NKV - 1);
    int t  = (idx >> 8) & (T_ - 1);
    int b  = idx >> 19;
    float inv = powf(10000.0f, -(float)j / 64.0f);
    float s, c;
    sincosf((float)t * inv, &s, &c);
    const float* src = g_ko + (size_t)(b * T_ + t) * (NKV * HD) + kh * HD;
    float x1 = src[j], x2 = src[j + 64];
    size_t o = ((size_t)(b * NKV + kh) * T_ + t) * HD;
    g_kpf[o + j]      = __float2half_rn(x1 * c - x2 * s);
    g_kpf[o + j + 64] = __float2half_rn(x2 * c + x1 * s);
}

// ---------------------------------------------------------------------------
// V transpose: fp32 [b*T+t][kh*128+d] -> single fp16 [(b,kh)*128+d][T]
// ---------------------------------------------------------------------------
__global__ void vt_kernel() {
    __shared__ float tl[32][33];
    int tx = threadIdx.x, ty = threadIdx.y;
    int t0 = blockIdx.x * 32, d0 = blockIdx.y * 32, bk = blockIdx.z;
    int b = bk >> 2, kh = bk & 3;
#pragma unroll
    for (int i = 0; i < 4; ++i)
        tl[ty + 8 * i][tx] =
            g_vo[(size_t)(b * T_ + t0 + ty + 8 * i) * (NKV * HD) + kh * HD + d0 + tx];
    __syncthreads();
#pragma unroll
    for (int i = 0; i < 4; ++i) {
        int dd = ty + 8 * i;
        g_vtf[((size_t)bk * HD + d0 + dd) * T_ + t0 + tx] = __float2half_rn(tl[tx][dd]);
    }
}

// ---------------------------------------------------------------------------
// Flash attention: S fp16 1-pass, PV fp16 1-pass, register softmax,
// double-buffered cp.async K/V. 8 warps x 16 q-rows, BN=64.
// ---------------------------------------------------------------------------
#define KSTR 68   // u32 per Q/K row (272 B)
#define VSTR 36   // u32 per V row (144 B)

struct FlashSmem5 {
    uint32_t Qf[128 * KSTR];
    uint32_t Kf[2][64 * KSTR];
    uint32_t Vf[2][128 * VSTR];
};
static_assert(sizeof(FlashSmem5) <= 227 * 1024, "smem too big");

__global__ __launch_bounds__(256, 1) void flash_mma(float* dummy) {
    extern __shared__ unsigned char smraw[];
    FlashSmem5& sm = *reinterpret_cast<FlashSmem5*>(smraw);
    const int tid = threadIdx.x;
    const int lane = tid & 31, w = tid >> 5;
    const int g = lane >> 2, tg = lane & 3;
    const int b = blockIdx.z, h = blockIdx.y;
    const int q0 = blockIdx.x * 128;
    const int kh = h >> 2;

    const __half* Qfg = g_qpf + ((size_t)(b * NH + h) * T_ + q0) * HD;
    const __half* Kfg = g_kpf + (size_t)(b * NKV + kh) * T_ * HD;
    const __half* Vfg = g_vtf + (size_t)(b * NKV + kh) * HD * T_;

    // Q tile load
    for (int s = tid; s < 128 * 16; s += 256) {
        int row = s >> 4, c16 = s & 15;
        *(uint4*)&sm.Qf[row * KSTR + c16 * 4] = *(const uint4*)(Qfg + (size_t)row * HD + c16 * 8);
    }

    float o[16][4];
#pragma unroll
    for (int t = 0; t < 16; ++t)
#pragma unroll
        for (int r = 0; r < 4; ++r) o[t][r] = 0.f;
    float m0 = -1e30f, m1 = -1e30f, l0 = 0.f, l1 = 0.f;

    const int row0 = q0 + w * 16 + g;
    const int row1 = row0 + 8;
    const int ntiles = (q0 >> 6) + 2;

    auto issue_tile = [&](int kt) {
        const int k0 = kt * 64;
        const int bi = kt & 1;
        const uint32_t kfb = smem_u32(sm.Kf[bi]);
        const uint32_t vfb = smem_u32(sm.Vf[bi]);
        for (int s = tid; s < 64 * 16; s += 256) {
            int row = s >> 4, c16 = s & 15;
            CP_ASYNC16(kfb + (row * KSTR + c16 * 4) * 4,
                       Kfg + (size_t)(k0 + row) * HD + c16 * 8);
        }
        for (int s = tid; s < 128 * 8; s += 256) {
            int d = s >> 3, c8 = s & 7;
            CP_ASYNC16(vfb + (d * VSTR + c8 * 4) * 4,
                       Vfg + (size_t)d * T_ + k0 + c8 * 8);
        }
        CP_COMMIT();
    };

    issue_tile(0);

    for (int kt = 0; kt < ntiles; ++kt) {
        const int k0 = kt * 64;
        if (kt + 1 < ntiles) { issue_tile(kt + 1); CP_WAIT1(); }
        else                 { CP_WAIT0(); }
        __syncthreads();

        const uint32_t* KfB = sm.Kf[kt & 1];
        const uint32_t* VfB = sm.Vf[kt & 1];

        // ---- S = Q K^T (fp16 single-pass), warp tile 16x64 ----
        float cs[8][4];
#pragma unroll
        for (int nj = 0; nj < 8; ++nj)
#pragma unroll
            for (int r = 0; r < 4; ++r) cs[nj][r] = 0.f;

#pragma unroll
        for (int kf = 0; kf < 8; ++kf) {
            uint32_t qf[4];
            int ab = (w * 16 + g) * KSTR + kf * 8 + tg;
            qf[0] = sm.Qf[ab];            qf[1] = sm.Qf[ab + 8 * KSTR];
            qf[2] = sm.Qf[ab + 4];        qf[3] = sm.Qf[ab + 8 * KSTR + 4];
#pragma unroll
            for (int nj = 0; nj < 8; ++nj) {
                int bb = (nj * 8 + g) * KSTR + kf * 8 + tg;
                uint32_t k2[2] = { KfB[bb], KfB[bb + 4] };
                mma_f16(cs[nj], qf, k2);
            }
        }

        // ---- causal mask ----
#pragma unroll
        for (int nj = 0; nj < 8; ++nj) {
            int c0 = k0 + nj * 8 + tg * 2, c1 = c0 + 1;
            cs[nj][0] = (c0 <= row0) ? cs[nj][0] : -1e30f;
            cs[nj][1] = (c1 <= row0) ? cs[nj][1] : -1e30f;
            cs[nj][2] = (c0 <= row1) ? cs[nj][2] : -1e30f;
            cs[nj][3] = (c1 <= row1) ? cs[nj][3] : -1e30f;
        }

        // ---- register softmax ----
        float mx0 = -1e30f, mx1 = -1e30f;
#pragma unroll
        for (int nj = 0; nj < 8; ++nj) {
            mx0 = fmaxf(mx0, fmaxf(cs[nj][0], cs[nj][1]));
            mx1 = fmaxf(mx1, fmaxf(cs[nj][2], cs[nj][3]));
        }
        mx0 = fmaxf(mx0, __shfl_xor_sync(0xffffffffu, mx0, 1));
        mx0 = fmaxf(mx0, __shfl_xor_sync(0xffffffffu, mx0, 2));
        mx1 = fmaxf(mx1, __shfl_xor_sync(0xffffffffu, mx1, 1));
        mx1 = fmaxf(mx1, __shfl_xor_sync(0xffffffffu, mx1, 2));

        float mn0 = fmaxf(m0, mx0), mn1 = fmaxf(m1, mx1);
        float al0 = __expf(m0 - mn0), al1 = __expf(m1 - mn1);
        float s0 = 0.f, s1 = 0.f;
#pragma unroll
        for (int nj = 0; nj < 8; ++nj) {
            cs[nj][0] = __expf(cs[nj][0] - mn0);
            cs[nj][1] = __expf(cs[nj][1] - mn0);
            cs[nj][2] = __expf(cs[nj][2] - mn1);
            cs[nj][3] = __expf(cs[nj][3] - mn1);
            s0 += cs[nj][0] + cs[nj][1];
            s1 += cs[nj][2] + cs[nj][3];
        }
        s0 += __shfl_xor_sync(0xffffffffu, s0, 1);
        s0 += __shfl_xor_sync(0xffffffffu, s0, 2);
        s1 += __shfl_xor_sync(0xffffffffu, s1, 1);
        s1 += __shfl_xor_sync(0xffffffffu, s1, 2);
        l0 = l0 * al0 + s0;
        l1 = l1 * al1 + s1;
        m0 = mn0; m1 = mn1;

#pragma unroll
        for (int t = 0; t < 16; ++t) {
            o[t][0] *= al0; o[t][1] *= al0;
            o[t][2] *= al1; o[t][3] *= al1;
        }

        // ---- O += P V (fp16 single-pass) ----
#pragma unroll
        for (int kf = 0; kf < 4; ++kf) {
            uint32_t pa[4];
            pa[0] = h2pack(cs[2 * kf][0],     cs[2 * kf][1]);
            pa[1] = h2pack(cs[2 * kf][2],     cs[2 * kf][3]);
            pa[2] = h2pack(cs[2 * kf + 1][0], cs[2 * kf + 1][1]);
            pa[3] = h2pack(cs[2 * kf + 1][2], cs[2 * kf + 1][3]);
#pragma unroll
            for (int nj = 0; nj < 16; ++nj) {
                int bb = (nj * 8 + g) * VSTR + kf * 8 + tg;
                uint32_t bv[2] = { VfB[bb], VfB[bb + 4] };
                mma_f16(o[nj], pa, bv);
            }
        }
        __syncthreads();
    }

    // ---- epilogue: normalize, write single fp16 attn plane ----
    float i0 = 1.0f / l0, i1 = 1.0f / l1;
    int r0 = q0 + w * 16 + g, r1 = r0 + 8;
#pragma unroll
    for (int nj = 0; nj < 16; ++nj) {
        int col = nj * 8 + tg * 2;
        size_t o0 = (size_t)(b * T_ + r0) * HID + h * HD + col;
        size_t o1 = (size_t)(b * T_ + r1) * HID + h * HD + col;
        *(__half2*)&g_af[o0] = __floats2half2_rn(o[nj][0] * i0, o[nj][1] * i0);
        *(__half2*)&g_af[o1] = __floats2half2_rn(o[nj][2] * i1, o[nj][3] * i1);
    }
    (void)dummy;
}

// ---------------------------------------------------------------------------
// Launch
// ---------------------------------------------------------------------------
extern "C" void kernel_launch(void* const* d_in, const int* in_sizes, int n_in,
                              void* d_out, int out_size) {
    const float* x  = (const float*)d_in[0];
    const float* Wq = (const float*)d_in[2];
    const float* Wk = (const float*)d_in[3];
    const float* Wv = (const float*)d_in[4];
    const float* Wo = (const float*)d_in[5];
    float* out = (float*)d_out;

    void *p_qo, *p_ko, *p_vo;
    void *p_xf, *p_wqf, *p_wkf, *p_wvf, *p_wof;
    void *p_af;
    cudaGetSymbolAddress(&p_qo, g_qo);
    cudaGetSymbolAddress(&p_ko, g_ko);
    cudaGetSymbolAddress(&p_vo, g_vo);
    cudaGetSymbolAddress(&p_xf, g_xf);
    cudaGetSymbolAddress(&p_wqf, g_wqf);
    cudaGetSymbolAddress(&p_wkf, g_wkf);
    cudaGetSymbolAddress(&p_wvf, g_wvf);
    cudaGetSymbolAddress(&p_wof, g_wof);
    cudaGetSymbolAddress(&p_af, g_af);

    cudaFuncSetAttribute(flash_mma, cudaFuncAttributeMaxDynamicSharedMemorySize,
                         (int)sizeof(FlashSmem5));

    // Splits (all single fp16)
    splitf_kernel<<<8192, 256>>>(x,  (__half*)p_xf,  B_ * T_ * HID / 4);
    splitf_kernel<<<4096, 256>>>(Wq, (__half*)p_wqf, HID * HID / 4);
    splitf_kernel<<<1024, 256>>>(Wk, (__half*)p_wkf, NKV * HD * HID / 4);
    splitf_kernel<<<1024, 256>>>(Wv, (__half*)p_wvf, NKV * HD * HID / 4);
    splitf_kernel<<<4096, 256>>>(Wo, (__half*)p_wof, HID * HID / 4);

    // QKV projections (fp16 single-pass)
    gemm_f16s<<<dim3(16, 32), 256>>>((const __half*)p_xf, (const __half*)p_wqf,
                                     (float*)p_qo, B_ * T_, NH * HD, HID);
    gemm_f16s<<<dim3(4, 32), 256>>>((const __half*)p_xf, (const __half*)p_wkf,
                                    (float*)p_ko, B_ * T_, NKV * HD, HID);
    gemm_f16s<<<dim3(4, 32), 256>>>((const __half*)p_xf, (const __half*)p_wvf,
                                    (float*)p_vo, B_ * T_, NKV * HD, HID);

    // RoPE + V transpose
    rope_q_kernel<<<(B_ * T_ * NH * 64) / 256, 256>>>();
    rope_k_kernel<<<(B_ * T_ * NKV * 64) / 256, 256>>>();
    vt_kernel<<<dim3(T_ / 32, HD / 32, B_ * NKV), dim3(32, 8)>>>();

    // Flash attention (writes single fp16 attn)
    flash_mma<<<dim3(T_ / 128, NH, B_), 256, sizeof(FlashSmem5)>>>(nullptr);

    // Output projection (fp16 single-pass)
    gemm_f16s<<<dim3(16, 32), 256>>>((const __half*)p_af, (const __half*)p_wof,
                                     out, B_ * T_, HID, HID);
}

// round 17
// speedup vs baseline: 5.3375x; 1.1244x over previous
#include <cuda_runtime.h>
#include <cuda_bf16.h>
#include <cuda_fp16.h>
#include <math.h>
#include <cstdint>

#define B_   2
#define T_   2048
#define HID  2048
#define NH   16
#define NKV  4
#define HD   128

// ---------------------------------------------------------------------------
// Global scratch
// ---------------------------------------------------------------------------
__device__ __align__(256) float g_qo[(size_t)B_ * T_ * NH * HD];
__device__ __align__(256) float g_kvo[(size_t)B_ * T_ * 2 * NKV * HD];   // K|V merged [4096,1024]

__device__ __align__(256) __half g_xf[(size_t)B_ * T_ * HID];
__device__ __align__(256) __half g_wqf[(size_t)HID * HID];
__device__ __align__(256) __half g_wkvf[(size_t)2 * NKV * HD * HID];     // Wk|Wv [1024,2048]
__device__ __align__(256) __half g_wof[(size_t)HID * HID];

__device__ __align__(256) __half g_qpf[(size_t)B_ * NH * T_ * HD];
__device__ __align__(256) __half g_kpf[(size_t)B_ * NKV * T_ * HD];
__device__ __align__(256) __half g_vtf[(size_t)B_ * NKV * HD * T_];
__device__ __align__(256) __half g_af[(size_t)B_ * T_ * HID];

// ---------------------------------------------------------------------------
// Helpers
// ---------------------------------------------------------------------------
__device__ __forceinline__ uint32_t smem_u32(const void* p) {
    uint32_t a;
    asm("{ .reg .u64 t; cvta.to.shared.u64 t, %1; cvt.u32.u64 %0, t; }"
        : "=r"(a) : "l"(p));
    return a;
}

#define CP_ASYNC16(dst, src) \
    asm volatile("cp.async.cg.shared.global [%0], [%1], 16;" :: "r"(dst), "l"(src))
#define CP_COMMIT() asm volatile("cp.async.commit_group;" ::: "memory")
#define CP_WAIT0()  asm volatile("cp.async.wait_group 0;" ::: "memory")
#define CP_WAIT1()  asm volatile("cp.async.wait_group 1;" ::: "memory")

__device__ __forceinline__ void mma_f16(float* c, const uint32_t* a, const uint32_t* b) {
    asm volatile(
        "mma.sync.aligned.m16n8k16.row.col.f32.f16.f16.f32 "
        "{%0,%1,%2,%3}, {%4,%5,%6,%7}, {%8,%9}, {%0,%1,%2,%3};"
        : "+f"(c[0]), "+f"(c[1]), "+f"(c[2]), "+f"(c[3])
        : "r"(a[0]), "r"(a[1]), "r"(a[2]), "r"(a[3]), "r"(b[0]), "r"(b[1]));
}

__device__ __forceinline__ uint32_t h2pack(float a, float b) {
    __half2 h = __floats2half2_rn(a, b);
    return *(uint32_t*)&h;
}

// ---------------------------------------------------------------------------
// Split pass: fp32 -> single fp16
// ---------------------------------------------------------------------------
__global__ void splitf_kernel(const float* __restrict__ in, __half* __restrict__ o, int n4) {
    int i = blockIdx.x * 256 + threadIdx.x;
    if (i >= n4) return;
    float4 v = ((const float4*)in)[i];
    ((__half2*)o)[2 * i]     = __floats2half2_rn(v.x, v.y);
    ((__half2*)o)[2 * i + 1] = __floats2half2_rn(v.z, v.w);
}

// ---------------------------------------------------------------------------
// GEMM NT fp16 single-pass, BK=32: C = A @ B^T
// 128x128 tile, 8 warps (2m x 4n), cp.async double-buffered.
// smem row = 32 halves + pad = 20 u32 (80 B: 16-mult, bank-tiling clean).
// ---------------------------------------------------------------------------
#define GSTR 20
#define GPLANE (128 * GSTR)

__global__ __launch_bounds__(256) void gemm_f16s(const __half* __restrict__ Af,
                                                 const __half* __restrict__ Bf,
                                                 float* __restrict__ C,
                                                 int M, int N_, int K) {
    __shared__ __align__(16) uint32_t sm[2][2][GPLANE];   // 40 KB
    const int tid = threadIdx.x;
    const int lane = tid & 31, wid = tid >> 5;
    const int g = lane >> 2, tg = lane & 3;
    const int m0 = blockIdx.y * 128, n0 = blockIdx.x * 128;
    const int mw = (wid >> 2) * 64, nw = (wid & 3) * 32;

    float acc[4][4][4];
#pragma unroll
    for (int mi = 0; mi < 4; ++mi)
#pragma unroll
        for (int nj = 0; nj < 4; ++nj)
#pragma unroll
            for (int r = 0; r < 4; ++r) acc[mi][nj][r] = 0.f;

    // 512 16B-chunks per plane (128 rows x 4 chunks); 2 chunks/thread/plane
    int rowL[2], colL[2], c4L[2];
#pragma unroll
    for (int u = 0; u < 2; ++u) {
        int s = tid * 2 + u;
        rowL[u] = s >> 2;            // 0..127
        colL[u] = (s & 3) * 8;       // halves 0,8,16,24
        c4L[u]  = (s & 3) * 4;       // u32 offset
    }
    const __half* srcA[2];
    const __half* srcB[2];
    uint32_t dstA[2], dstB[2];
#pragma unroll
    for (int u = 0; u < 2; ++u) {
        srcA[u] = Af + (size_t)(m0 + rowL[u]) * K + colL[u];
        srcB[u] = Bf + (size_t)(n0 + rowL[u]) * K + colL[u];
        dstA[u] = smem_u32(&sm[0][0][rowL[u] * GSTR + c4L[u]]);
        dstB[u] = smem_u32(&sm[0][1][rowL[u] * GSTR + c4L[u]]);
    }
    const uint32_t bufB = 2 * GPLANE * 4;

#pragma unroll
    for (int u = 0; u < 2; ++u) { CP_ASYNC16(dstA[u], srcA[u]); CP_ASYNC16(dstB[u], srcB[u]); }
    CP_COMMIT();

    const int nkt = K >> 5;
    for (int kt = 0; kt < nkt; ++kt) {
        CP_WAIT0();
        __syncthreads();
        if (kt + 1 < nkt) {
            const int k0 = (kt + 1) << 5;
            const uint32_t bo = ((kt + 1) & 1) * bufB;
#pragma unroll
            for (int u = 0; u < 2; ++u) {
                CP_ASYNC16(dstA[u] + bo, srcA[u] + k0);
                CP_ASYNC16(dstB[u] + bo, srcB[u] + k0);
            }
            CP_COMMIT();
        }
        const uint32_t (*cur)[GPLANE] = sm[kt & 1];

#pragma unroll
        for (int kf = 0; kf < 2; ++kf) {
            uint32_t ah[4][4], bh[4][2];
#pragma unroll
            for (int mi = 0; mi < 4; ++mi) {
                int base = (mw + mi * 16 + g) * GSTR + kf * 8 + tg;
                ah[mi][0] = cur[0][base];      ah[mi][1] = cur[0][base + 8 * GSTR];
                ah[mi][2] = cur[0][base + 4];  ah[mi][3] = cur[0][base + 8 * GSTR + 4];
            }
#pragma unroll
            for (int nj = 0; nj < 4; ++nj) {
                int base = (nw + nj * 8 + g) * GSTR + kf * 8 + tg;
                bh[nj][0] = cur[1][base]; bh[nj][1] = cur[1][base + 4];
            }
#pragma unroll
            for (int mi = 0; mi < 4; ++mi)
#pragma unroll
                for (int nj = 0; nj < 4; ++nj)
                    mma_f16(acc[mi][nj], ah[mi], bh[nj]);
        }
    }

#pragma unroll
    for (int mi = 0; mi < 4; ++mi) {
#pragma unroll
        for (int nj = 0; nj < 4; ++nj) {
            int row = m0 + mw + mi * 16 + g;
            int col = n0 + nw + nj * 8 + tg * 2;
            *(float2*)(C + (size_t)row * N_ + col) =
                make_float2(acc[mi][nj][0], acc[mi][nj][1]);
            *(float2*)(C + (size_t)(row + 8) * N_ + col) =
                make_float2(acc[mi][nj][2], acc[mi][nj][3]);
        }
    }
}

// ---------------------------------------------------------------------------
// RoPE: Q (from g_qo) and K (from merged g_kvo) -> single fp16 planes
// ---------------------------------------------------------------------------
__global__ void rope_q_kernel() {
    int idx = blockIdx.x * 256 + threadIdx.x;
    int j = idx & 63;
    int h = (idx >> 6) & (NH - 1);
    int t = (idx >> 10) & (T_ - 1);
    int b = idx >> 21;
    float inv = powf(10000.0f, -(float)j / 64.0f);
    float s, c;
    sincosf((float)t * inv, &s, &c);
    const float scale = 0.08838834764831845f;
    const float* src = g_qo + (size_t)(b * T_ + t) * (NH * HD) + h * HD;
    float x1 = src[j], x2 = src[j + 64];
    size_t o = ((size_t)(b * NH + h) * T_ + t) * HD;
    g_qpf[o + j]      = __float2half_rn((x1 * c - x2 * s) * scale);
    g_qpf[o + j + 64] = __float2half_rn((x2 * c + x1 * s) * scale);
}

__global__ void rope_k_kernel() {
    int idx = blockIdx.x * 256 + threadIdx.x;
    int j  = idx & 63;
    int kh = (idx >> 6) & (NKV - 1);
    int t  = (idx >> 8) & (T_ - 1);
    int b  = idx >> 19;
    float inv = powf(10000.0f, -(float)j / 64.0f);
    float s, c;
    sincosf((float)t * inv, &s, &c);
    const float* src = g_kvo + (size_t)(b * T_ + t) * (2 * NKV * HD) + kh * HD;
    float x1 = src[j], x2 = src[j + 64];
    size_t o = ((size_t)(b * NKV + kh) * T_ + t) * HD;
    g_kpf[o + j]      = __float2half_rn(x1 * c - x2 * s);
    g_kpf[o + j + 64] = __float2half_rn(x2 * c + x1 * s);
}

// ---------------------------------------------------------------------------
// V transpose from merged g_kvo (V at col offset 512): -> fp16 [(b,kh)*128+d][T]
// ---------------------------------------------------------------------------
__global__ void vt_kernel() {
    __shared__ float tl[32][33];
    int tx = threadIdx.x, ty = threadIdx.y;
    int t0 = blockIdx.x * 32, d0 = blockIdx.y * 32, bk = blockIdx.z;
    int b = bk >> 2, kh = bk & 3;
#pragma unroll
    for (int i = 0; i < 4; ++i)
        tl[ty + 8 * i][tx] =
            g_kvo[(size_t)(b * T_ + t0 + ty + 8 * i) * (2 * NKV * HD)
                  + NKV * HD + kh * HD + d0 + tx];
    __syncthreads();
#pragma unroll
    for (int i = 0; i < 4; ++i) {
        int dd = ty + 8 * i;
        g_vtf[((size_t)bk * HD + d0 + dd) * T_ + t0 + tx] = __float2half_rn(tl[tx][dd]);
    }
}

// ---------------------------------------------------------------------------
// Flash attention: S fp16 1-pass, PV fp16 1-pass, register softmax,
// double-buffered cp.async K/V. 8 warps x 16 q-rows, BN=64. (unchanged)
// ---------------------------------------------------------------------------
#define KSTR 68   // u32 per Q/K row (272 B)
#define VSTR 36   // u32 per V row (144 B)

struct FlashSmem5 {
    uint32_t Qf[128 * KSTR];
    uint32_t Kf[2][64 * KSTR];
    uint32_t Vf[2][128 * VSTR];
};
static_assert(sizeof(FlashSmem5) <= 227 * 1024, "smem too big");

__global__ __launch_bounds__(256, 1) void flash_mma(float* dummy) {
    extern __shared__ unsigned char smraw[];
    FlashSmem5& sm = *reinterpret_cast<FlashSmem5*>(smraw);
    const int tid = threadIdx.x;
    const int lane = tid & 31, w = tid >> 5;
    const int g = lane >> 2, tg = lane & 3;
    const int b = blockIdx.z, h = blockIdx.y;
    const int q0 = blockIdx.x * 128;
    const int kh = h >> 2;

    const __half* Qfg = g_qpf + ((size_t)(b * NH + h) * T_ + q0) * HD;
    const __half* Kfg = g_kpf + (size_t)(b * NKV + kh) * T_ * HD;
    const __half* Vfg = g_vtf + (size_t)(b * NKV + kh) * HD * T_;

    for (int s = tid; s < 128 * 16; s += 256) {
        int row = s >> 4, c16 = s & 15;
        *(uint4*)&sm.Qf[row * KSTR + c16 * 4] = *(const uint4*)(Qfg + (size_t)row * HD + c16 * 8);
    }

    float o[16][4];
#pragma unroll
    for (int t = 0; t < 16; ++t)
#pragma unroll
        for (int r = 0; r < 4; ++r) o[t][r] = 0.f;
    float m0 = -1e30f, m1 = -1e30f, l0 = 0.f, l1 = 0.f;

    const int row0 = q0 + w * 16 + g;
    const int row1 = row0 + 8;
    const int ntiles = (q0 >> 6) + 2;

    auto issue_tile = [&](int kt) {
        const int k0 = kt * 64;
        const int bi = kt & 1;
        const uint32_t kfb = smem_u32(sm.Kf[bi]);
        const uint32_t vfb = smem_u32(sm.Vf[bi]);
        for (int s = tid; s < 64 * 16; s += 256) {
            int row = s >> 4, c16 = s & 15;
            CP_ASYNC16(kfb + (row * KSTR + c16 * 4) * 4,
                       Kfg + (size_t)(k0 + row) * HD + c16 * 8);
        }
        for (int s = tid; s < 128 * 8; s += 256) {
            int d = s >> 3, c8 = s & 7;
            CP_ASYNC16(vfb + (d * VSTR + c8 * 4) * 4,
                       Vfg + (size_t)d * T_ + k0 + c8 * 8);
        }
        CP_COMMIT();
    };

    issue_tile(0);

    for (int kt = 0; kt < ntiles; ++kt) {
        const int k0 = kt * 64;
        if (kt + 1 < ntiles) { issue_tile(kt + 1); CP_WAIT1(); }
        else                 { CP_WAIT0(); }
        __syncthreads();

        const uint32_t* KfB = sm.Kf[kt & 1];
        const uint32_t* VfB = sm.Vf[kt & 1];

        float cs[8][4];
#pragma unroll
        for (int nj = 0; nj < 8; ++nj)
#pragma unroll
            for (int r = 0; r < 4; ++r) cs[nj][r] = 0.f;

#pragma unroll
        for (int kf = 0; kf < 8; ++kf) {
            uint32_t qf[4];
            int ab = (w * 16 + g) * KSTR + kf * 8 + tg;
            qf[0] = sm.Qf[ab];            qf[1] = sm.Qf[ab + 8 * KSTR];
            qf[2] = sm.Qf[ab + 4];        qf[3] = sm.Qf[ab + 8 * KSTR + 4];
#pragma unroll
            for (int nj = 0; nj < 8; ++nj) {
                int bb = (nj * 8 + g) * KSTR + kf * 8 + tg;
                uint32_t k2[2] = { KfB[bb], KfB[bb + 4] };
                mma_f16(cs[nj], qf, k2);
            }
        }

#pragma unroll
        for (int nj = 0; nj < 8; ++nj) {
            int c0 = k0 + nj * 8 + tg * 2, c1 = c0 + 1;
            cs[nj][0] = (c0 <= row0) ? cs[nj][0] : -1e30f;
            cs[nj][1] = (c1 <= row0) ? cs[nj][1] : -1e30f;
            cs[nj][2] = (c0 <= row1) ? cs[nj][2] : -1e30f;
            cs[nj][3] = (c1 <= row1) ? cs[nj][3] : -1e30f;
        }

        float mx0 = -1e30f, mx1 = -1e30f;
#pragma unroll
        for (int nj = 0; nj < 8; ++nj) {
            mx0 = fmaxf(mx0, fmaxf(cs[nj][0], cs[nj][1]));
            mx1 = fmaxf(mx1, fmaxf(cs[nj][2], cs[nj][3]));
        }
        mx0 = fmaxf(mx0, __shfl_xor_sync(0xffffffffu, mx0, 1));
        mx0 = fmaxf(mx0, __shfl_xor_sync(0xffffffffu, mx0, 2));
        mx1 = fmaxf(mx1, __shfl_xor_sync(0xffffffffu, mx1, 1));
        mx1 = fmaxf(mx1, __shfl_xor_sync(0xffffffffu, mx1, 2));

        float mn0 = fmaxf(m0, mx0), mn1 = fmaxf(m1, mx1);
        float al0 = __expf(m0 - mn0), al1 = __expf(m1 - mn1);
        float s0 = 0.f, s1 = 0.f;
#pragma unroll
        for (int nj = 0; nj < 8; ++nj) {
            cs[nj][0] = __expf(cs[nj][0] - mn0);
            cs[nj][1] = __expf(cs[nj][1] - mn0);
            cs[nj][2] = __expf(cs[nj][2] - mn1);
            cs[nj][3] = __expf(cs[nj][3] - mn1);
            s0 += cs[nj][0] + cs[nj][1];
            s1 += cs[nj][2] + cs[nj][3];
        }
        s0 += __shfl_xor_sync(0xffffffffu, s0, 1);
        s0 += __shfl_xor_sync(0xffffffffu, s0, 2);
        s1 += __shfl_xor_sync(0xffffffffu, s1, 1);
        s1 += __shfl_xor_sync(0xffffffffu, s1, 2);
        l0 = l0 * al0 + s0;
        l1 = l1 * al1 + s1;
        m0 = mn0; m1 = mn1;

#pragma unroll
        for (int t = 0; t < 16; ++t) {
            o[t][0] *= al0; o[t][1] *= al0;
            o[t][2] *= al1; o[t][3] *= al1;
        }

#pragma unroll
        for (int kf = 0; kf < 4; ++kf) {
            uint32_t pa[4];
            pa[0] = h2pack(cs[2 * kf][0],     cs[2 * kf][1]);
            pa[1] = h2pack(cs[2 * kf][2],     cs[2 * kf][3]);
            pa[2] = h2pack(cs[2 * kf + 1][0], cs[2 * kf + 1][1]);
            pa[3] = h2pack(cs[2 * kf + 1][2], cs[2 * kf + 1][3]);
#pragma unroll
            for (int nj = 0; nj < 16; ++nj) {
                int bb = (nj * 8 + g) * VSTR + kf * 8 + tg;
                uint32_t bv[2] = { VfB[bb], VfB[bb + 4] };
                mma_f16(o[nj], pa, bv);
            }
        }
        __syncthreads();
    }

    float i0 = 1.0f / l0, i1 = 1.0f / l1;
    int r0 = q0 + w * 16 + g, r1 = r0 + 8;
#pragma unroll
    for (int nj = 0; nj < 16; ++nj) {
        int col = nj * 8 + tg * 2;
        size_t o0 = (size_t)(b * T_ + r0) * HID + h * HD + col;
        size_t o1 = (size_t)(b * T_ + r1) * HID + h * HD + col;
        *(__half2*)&g_af[o0] = __floats2half2_rn(o[nj][0] * i0, o[nj][1] * i0);
        *(__half2*)&g_af[o1] = __floats2half2_rn(o[nj][2] * i1, o[nj][3] * i1);
    }
    (void)dummy;
}

// ---------------------------------------------------------------------------
// Launch
// ---------------------------------------------------------------------------
extern "C" void kernel_launch(void* const* d_in, const int* in_sizes, int n_in,
                              void* d_out, int out_size) {
    const float* x  = (const float*)d_in[0];
    const float* Wq = (const float*)d_in[2];
    const float* Wk = (const float*)d_in[3];
    const float* Wv = (const float*)d_in[4];
    const float* Wo = (const float*)d_in[5];
    float* out = (float*)d_out;

    void *p_qo, *p_kvo;
    void *p_xf, *p_wqf, *p_wkvf, *p_wof;
    void *p_af;
    cudaGetSymbolAddress(&p_qo, g_qo);
    cudaGetSymbolAddress(&p_kvo, g_kvo);
    cudaGetSymbolAddress(&p_xf, g_xf);
    cudaGetSymbolAddress(&p_wqf, g_wqf);
    cudaGetSymbolAddress(&p_wkvf, g_wkvf);
    cudaGetSymbolAddress(&p_wof, g_wof);
    cudaGetSymbolAddress(&p_af, g_af);

    cudaFuncSetAttribute(flash_mma, cudaFuncAttributeMaxDynamicSharedMemorySize,
                         (int)sizeof(FlashSmem5));

    // Splits (all single fp16); Wk and Wv pack into one [1024,2048] weight
    splitf_kernel<<<8192, 256>>>(x,  (__half*)p_xf,  B_ * T_ * HID / 4);
    splitf_kernel<<<4096, 256>>>(Wq, (__half*)p_wqf, HID * HID / 4);
    splitf_kernel<<<1024, 256>>>(Wk, (__half*)p_wkvf, NKV * HD * HID / 4);
    splitf_kernel<<<1024, 256>>>(Wv, (__half*)p_wkvf + (size_t)NKV * HD * HID,
                                 NKV * HD * HID / 4);
    splitf_kernel<<<4096, 256>>>(Wo, (__half*)p_wof, HID * HID / 4);

    // Projections (fp16 single-pass, BK=32)
    gemm_f16s<<<dim3(16, 32), 256>>>((const __half*)p_xf, (const __half*)p_wqf,
                                     (float*)p_qo, B_ * T_, NH * HD, HID);
    gemm_f16s<<<dim3(8, 32), 256>>>((const __half*)p_xf, (const __half*)p_wkvf,
                                    (float*)p_kvo, B_ * T_, 2 * NKV * HD, HID);

    // RoPE + V transpose (read from merged K|V output)
    rope_q_kernel<<<(B_ * T_ * NH * 64) / 256, 256>>>();
    rope_k_kernel<<<(B_ * T_ * NKV * 64) / 256, 256>>>();
    vt_kernel<<<dim3(T_ / 32, HD / 32, B_ * NKV), dim3(32, 8)>>>();

    // Flash attention
    flash_mma<<<dim3(T_ / 128, NH, B_), 256, sizeof(FlashSmem5)>>>(nullptr);

    // Output projection
    gemm_f16s<<<dim3(16, 32), 256>>>((const __half*)p_af, (const __half*)p_wof,
                                     out, B_ * T_, HID, HID);
}